// round 1
// baseline (speedup 1.0000x reference)
#include <cuda_runtime.h>
#include <cstdint>

#define B_EV 4
#define NP 8192
#define MP 2048
#define KNN 64
#define NC (B_EV * MP)          // 8192 centers
#define R2F 0.04f               // R=0.2
#define BIGF 1e10f
#define CAP 512                 // candidate buffer per center (lambda~274)

#define XLEN (NC * 128)         // x_out elements
#define POS_OFF XLEN
#define BATCH_OFF (XLEN + NC * 3)

// ---------------- scratch (device globals; no allocation allowed) ----------
__device__ float g_centers[NC * 3];
__device__ int   g_nbr[NC * KNN];
__device__ int   g_cnt[NC];

// Deterministic distance: no FMA contraction, ((x2+y2)+z2) order to match XLA.
__device__ __forceinline__ float dist2(float dx, float dy, float dz) {
    return __fadd_rn(__fadd_rn(__fmul_rn(dx, dx), __fmul_rn(dy, dy)),
                     __fmul_rn(dz, dz));
}

// ---------------- packed f32x2 helpers -------------------------------------
#define FMA2(acc, a, b) \
    asm("fma.rn.f32x2 %0, %1, %2, %0;" : "+l"(acc) : "l"(a), "l"(b))

__device__ __forceinline__ unsigned long long pack2(float v) {
    unsigned long long r;
    asm("mov.b64 %0, {%1, %1};" : "=l"(r) : "r"(__float_as_uint(v)));
    return r;
}
__device__ __forceinline__ float2 unpack2(unsigned long long p) {
    unsigned lo, hi;
    asm("mov.b64 {%0, %1}, %2;" : "=r"(lo), "=r"(hi) : "l"(p));
    return make_float2(__uint_as_float(lo), __uint_as_float(hi));
}

// ============================================================================
// Kernel 1: farthest point sampling. One block per event, 1024 threads,
// 8 points per thread held in registers. Packed-u64 argmax: upper 32 = d bits
// (d >= 0 so float bits are order-preserving), lower 32 = ~idx so ties pick
// the LOWEST index (matches jnp.argmax).
// ============================================================================
__global__ __launch_bounds__(1024) void fps_kernel(const float* __restrict__ pos) {
    const int e = blockIdx.x;
    const float* pe = pos + (size_t)e * NP * 3;
    const int tid = threadIdx.x;

    float px[8], py[8], pz[8], d[8];
    const float c0x = pe[0], c0y = pe[1], c0z = pe[2];
#pragma unroll
    for (int t = 0; t < 8; t++) {
        const int j = tid + t * 1024;
        px[t] = pe[3 * j];
        py[t] = pe[3 * j + 1];
        pz[t] = pe[3 * j + 2];
        d[t] = dist2(px[t] - c0x, py[t] - c0y, pz[t] - c0z);
    }

    __shared__ unsigned long long red[32];
    __shared__ int s_next;

    if (tid == 0) {
        g_centers[(e * MP) * 3 + 0] = c0x;
        g_centers[(e * MP) * 3 + 1] = c0y;
        g_centers[(e * MP) * 3 + 2] = c0z;
    }

    for (int i = 1; i < MP; i++) {
        unsigned long long best = 0ull;
#pragma unroll
        for (int t = 0; t < 8; t++) {
            const unsigned long long key =
                ((unsigned long long)__float_as_uint(d[t]) << 32) |
                (unsigned)(~(tid + t * 1024));
            best = (key > best) ? key : best;
        }
#pragma unroll
        for (int o = 16; o > 0; o >>= 1) {
            const unsigned long long other = __shfl_down_sync(0xffffffffu, best, o);
            best = (other > best) ? other : best;
        }
        if ((tid & 31) == 0) red[tid >> 5] = best;
        __syncthreads();
        if (tid < 32) {
            best = red[tid];
#pragma unroll
            for (int o = 16; o > 0; o >>= 1) {
                const unsigned long long other = __shfl_down_sync(0xffffffffu, best, o);
                best = (other > best) ? other : best;
            }
            if (tid == 0) s_next = (int)(~(unsigned)best);
        }
        __syncthreads();

        const int nxt = s_next;
        const float nx = pe[3 * nxt], ny = pe[3 * nxt + 1], nz = pe[3 * nxt + 2];
        if (tid == 0) {
            g_centers[(e * MP + i) * 3 + 0] = nx;
            g_centers[(e * MP + i) * 3 + 1] = ny;
            g_centers[(e * MP + i) * 3 + 2] = nz;
        }
#pragma unroll
        for (int t = 0; t < 8; t++) {
            const float dd = dist2(px[t] - nx, py[t] - ny, pz[t] - nz);
            d[t] = fminf(d[t], dd);
        }
    }
}

// ============================================================================
// Kernel 2: ball query + top-K. Warp per center (8 centers / 256-thread block).
// Pass 1: compact all within-radius candidates into shared (ballot + popc).
// Pass 2: if C > K, 64 extract-min passes; key = (d2bits<<32)|slot so equal
// distances pick the lower original index (slots are in ascending-j order),
// matching lax.top_k stability.
// ============================================================================
__global__ __launch_bounds__(256) void bq_kernel(const float* __restrict__ pos) {
    __shared__ float s_d2[8][CAP];
    __shared__ int   s_idx[8][CAP];

    const int w = threadIdx.x >> 5;
    const int lane = threadIdx.x & 31;
    const int c = blockIdx.x * 8 + w;
    const int e = c >> 11;  // c / MP
    const float* pe = pos + (size_t)e * NP * 3;

    const float cx = g_centers[c * 3 + 0];
    const float cy = g_centers[c * 3 + 1];
    const float cz = g_centers[c * 3 + 2];

    int cnt = 0;
    const unsigned lmask = (1u << lane) - 1u;
    for (int j = lane; j < NP; j += 32) {
        const float d2v = dist2(pe[3 * j] - cx, pe[3 * j + 1] - cy, pe[3 * j + 2] - cz);
        const bool inr = (d2v <= R2F);
        const unsigned m = __ballot_sync(0xffffffffu, inr);
        if (inr) {
            const int slot = cnt + __popc(m & lmask);
            if (slot < CAP) { s_d2[w][slot] = d2v; s_idx[w][slot] = j; }
        }
        cnt += __popc(m);
    }
    const int C = (cnt < CAP) ? cnt : CAP;

    if (C <= KNN) {
        for (int k = lane; k < KNN; k += 32)
            g_nbr[c * KNN + k] = (k < C) ? s_idx[w][k] : 0;
        if (lane == 0) g_cnt[c] = C;
    } else {
        for (int s = 0; s < KNN; s++) {
            unsigned long long best = ~0ull;
            for (int t = lane; t < C; t += 32) {
                const unsigned long long key =
                    ((unsigned long long)__float_as_uint(s_d2[w][t]) << 32) | (unsigned)t;
                best = (key < best) ? key : best;
            }
#pragma unroll
            for (int o = 16; o > 0; o >>= 1) {
                const unsigned long long other = __shfl_down_sync(0xffffffffu, best, o);
                best = (other < best) ? other : best;
            }
            best = __shfl_sync(0xffffffffu, best, 0);
            const int slot = (int)(unsigned)best;
            if (lane == 0) {
                g_nbr[c * KNN + s] = s_idx[w][slot];
                s_d2[w][slot] = BIGF;
            }
            __syncwarp();
        }
        if (lane == 0) g_cnt[c] = KNN;
    }
}

// ============================================================================
// Kernel 3: gather + 3-layer MLP (35->64->64->128, ReLU) + max-pool.
// 2 centers per 128-thread block: thread = one neighbor slot. Weights in
// dynamic shared (broadcast LDS.128 -> two weight f32x2 per instr).
// Accumulation with packed fma.rn.f32x2 (2x fp32 rate vs FFMA 3-reg).
// h1/h2 register-resident (layer tile loops fully unrolled). Max-pool via
// shared atomicMax on float bits (all values >= 0 post-ReLU).
// ============================================================================
__global__ __launch_bounds__(128, 3) void mlp_kernel(
    const float* __restrict__ x, const float* __restrict__ pos,
    const float* __restrict__ W1, const float* __restrict__ b1,
    const float* __restrict__ W2, const float* __restrict__ b2,
    const float* __restrict__ W3, const float* __restrict__ b3,
    float* __restrict__ out)
{
    extern __shared__ float smem[];
    float* sW1 = smem;            // 35*64 = 2240
    float* sW2 = sW1 + 2240;      // 64*64 = 4096
    float* sW3 = sW2 + 4096;      // 64*128 = 8192
    float* sb1 = sW3 + 8192;      // 64
    float* sb2 = sb1 + 64;        // 64
    float* sb3 = sb2 + 64;        // 128
    int*   sOut = (int*)(sb3 + 128);  // 2*128

    const int tid = threadIdx.x;
    for (int i = tid; i < 2240; i += 128) sW1[i] = W1[i];
    for (int i = tid; i < 4096; i += 128) sW2[i] = W2[i];
    for (int i = tid; i < 8192; i += 128) sW3[i] = W3[i];
    if (tid < 64) { sb1[tid] = b1[tid]; sb2[tid] = b2[tid]; }
    sb3[tid] = b3[tid];
    sOut[tid] = 0;
    sOut[tid + 128] = 0;
    __syncthreads();

    const int cl = tid >> 6;          // which of the 2 centers
    const int n  = tid & 63;          // neighbor slot
    const int c  = blockIdx.x * 2 + cl;
    const int e  = c >> 11;
    const int cnt = g_cnt[c];
    int* sOutC = sOut + cl * 128;

    if (n < cnt) {
        const int idx = g_nbr[c * KNN + n];
        const int row = e * NP + idx;

        float inv[35];
        const float4* xr = (const float4*)(x + (size_t)row * 32);
#pragma unroll
        for (int q = 0; q < 8; q++) {
            const float4 v = xr[q];
            inv[4 * q + 0] = v.x; inv[4 * q + 1] = v.y;
            inv[4 * q + 2] = v.z; inv[4 * q + 3] = v.w;
        }
        inv[32] = pos[row * 3 + 0] - g_centers[c * 3 + 0];
        inv[33] = pos[row * 3 + 1] - g_centers[c * 3 + 1];
        inv[34] = pos[row * 3 + 2] - g_centers[c * 3 + 2];

        unsigned long long in2[35];
#pragma unroll
        for (int i = 0; i < 35; i++) in2[i] = pack2(inv[i]);

        // ---- layer 1: 35 -> 64 ----
        float h1[64];
#pragma unroll
        for (int kt = 0; kt < 16; kt++) {
            unsigned long long a01 = *(const unsigned long long*)(sb1 + kt * 4);
            unsigned long long a23 = *(const unsigned long long*)(sb1 + kt * 4 + 2);
#pragma unroll
            for (int i = 0; i < 35; i++) {
                const ulonglong2 wv = *(const ulonglong2*)(sW1 + i * 64 + kt * 4);
                FMA2(a01, in2[i], wv.x);
                FMA2(a23, in2[i], wv.y);
            }
            const float2 v01 = unpack2(a01), v23 = unpack2(a23);
            h1[4 * kt + 0] = fmaxf(v01.x, 0.f);
            h1[4 * kt + 1] = fmaxf(v01.y, 0.f);
            h1[4 * kt + 2] = fmaxf(v23.x, 0.f);
            h1[4 * kt + 3] = fmaxf(v23.y, 0.f);
        }

        // ---- layer 2: 64 -> 64 ----
        float h2[64];
#pragma unroll
        for (int kt = 0; kt < 16; kt++) {
            unsigned long long a01 = *(const unsigned long long*)(sb2 + kt * 4);
            unsigned long long a23 = *(const unsigned long long*)(sb2 + kt * 4 + 2);
#pragma unroll
            for (int i = 0; i < 64; i++) {
                const unsigned long long hp = pack2(h1[i]);
                const ulonglong2 wv = *(const ulonglong2*)(sW2 + i * 64 + kt * 4);
                FMA2(a01, hp, wv.x);
                FMA2(a23, hp, wv.y);
            }
            const float2 v01 = unpack2(a01), v23 = unpack2(a23);
            h2[4 * kt + 0] = fmaxf(v01.x, 0.f);
            h2[4 * kt + 1] = fmaxf(v01.y, 0.f);
            h2[4 * kt + 2] = fmaxf(v23.x, 0.f);
            h2[4 * kt + 3] = fmaxf(v23.y, 0.f);
        }

        // ---- layer 3: 64 -> 128, fused max-pool ----
        unsigned long long h2p[64];
#pragma unroll
        for (int i = 0; i < 64; i++) h2p[i] = pack2(h2[i]);

#pragma unroll 2
        for (int kt = 0; kt < 32; kt++) {
            unsigned long long a01 = *(const unsigned long long*)(sb3 + kt * 4);
            unsigned long long a23 = *(const unsigned long long*)(sb3 + kt * 4 + 2);
#pragma unroll
            for (int i = 0; i < 64; i++) {
                const ulonglong2 wv = *(const ulonglong2*)(sW3 + i * 128 + kt * 4);
                FMA2(a01, h2p[i], wv.x);
                FMA2(a23, h2p[i], wv.y);
            }
            const float2 v01 = unpack2(a01), v23 = unpack2(a23);
            atomicMax(sOutC + 4 * kt + 0, __float_as_int(fmaxf(v01.x, 0.f)));
            atomicMax(sOutC + 4 * kt + 1, __float_as_int(fmaxf(v01.y, 0.f)));
            atomicMax(sOutC + 4 * kt + 2, __float_as_int(fmaxf(v23.x, 0.f)));
            atomicMax(sOutC + 4 * kt + 3, __float_as_int(fmaxf(v23.y, 0.f)));
        }
    }
    __syncthreads();

    // ---- write outputs: [x_out | pos_out | batch_out] as float32 ----
    {
        int i = tid;
        int cc = blockIdx.x * 2 + (i >> 7);
        out[(size_t)cc * 128 + (i & 127)] = __int_as_float(sOut[i]);
        i = tid + 128;
        cc = blockIdx.x * 2 + (i >> 7);
        out[(size_t)cc * 128 + (i & 127)] = __int_as_float(sOut[i]);
    }
    if (tid < 6) {
        const int cc = blockIdx.x * 2 + (tid / 3);
        out[POS_OFF + (size_t)cc * 3 + (tid % 3)] = g_centers[cc * 3 + (tid % 3)];
    }
    if (tid < 2) {
        const int cc = blockIdx.x * 2 + tid;
        out[BATCH_OFF + cc] = (float)(cc >> 11);
    }
}

// ============================================================================
extern "C" void kernel_launch(void* const* d_in, const int* in_sizes, int n_in,
                              void* d_out, int out_size) {
    const float* x   = (const float*)d_in[0];
    const float* pos = (const float*)d_in[1];
    // d_in[2] = batch (int64) — unused (events are contiguous, NP each)
    const float* W1 = (const float*)d_in[3];
    const float* b1 = (const float*)d_in[4];
    const float* W2 = (const float*)d_in[5];
    const float* b2 = (const float*)d_in[6];
    const float* W3 = (const float*)d_in[7];
    const float* b3 = (const float*)d_in[8];
    float* out = (float*)d_out;

    fps_kernel<<<B_EV, 1024>>>(pos);
    bq_kernel<<<NC / 8, 256>>>(pos);

    const int smem_bytes = (2240 + 4096 + 8192 + 64 + 64 + 128 + 256) * 4; // 60160
    cudaFuncSetAttribute(mlp_kernel, cudaFuncAttributeMaxDynamicSharedMemorySize,
                         smem_bytes);
    mlp_kernel<<<NC / 2, 128, smem_bytes>>>(x, pos, W1, b1, W2, b2, W3, b3, out);
}

// round 2
// speedup vs baseline: 1.2468x; 1.2468x over previous
#include <cuda_runtime.h>
#include <cstdint>

#define B_EV 4
#define NP 8192
#define MP 2048
#define KNN 64
#define NC (B_EV * MP)          // 8192 centers
#define R2F 0.04f               // R=0.2
#define BIGF 1e10f
#define CAP 512

#define XLEN (NC * 128)
#define POS_OFF XLEN
#define BATCH_OFF (XLEN + NC * 3)

typedef unsigned long long ull;

// ---------------- scratch ---------------------------------------------------
__device__ float g_centers[NC * 3];
__device__ int   g_nbr[NC * KNN];
__device__ int   g_cnt[NC];

// Deterministic distance: no FMA contraction, ((x2+y2)+z2) order.
__device__ __forceinline__ float dist2(float dx, float dy, float dz) {
    return __fadd_rn(__fadd_rn(__fmul_rn(dx, dx), __fmul_rn(dy, dy)),
                     __fmul_rn(dz, dz));
}

// ---------------- packed f32x2 helpers (per-lane rn == scalar rn) -----------
#define FMA2(acc, a, b) \
    asm("fma.rn.f32x2 %0, %1, %2, %0;" : "+l"(acc) : "l"(a), "l"(b))
#define ADD2(dst, a, b) \
    asm("add.rn.f32x2 %0, %1, %2;" : "=l"(dst) : "l"(a), "l"(b))
#define MUL2(dst, a, b) \
    asm("mul.rn.f32x2 %0, %1, %2;" : "=l"(dst) : "l"(a), "l"(b))

__device__ __forceinline__ ull pack2(float v) {
    ull r;
    asm("mov.b64 %0, {%1, %1};" : "=l"(r) : "r"(__float_as_uint(v)));
    return r;
}
__device__ __forceinline__ ull packf2(float lo, float hi) {
    ull r;
    asm("mov.b64 %0, {%1, %2};" : "=l"(r)
        : "r"(__float_as_uint(lo)), "r"(__float_as_uint(hi)));
    return r;
}
__device__ __forceinline__ float2 unpack2(ull p) {
    unsigned lo, hi;
    asm("mov.b64 {%0, %1}, %2;" : "=r"(lo), "=r"(hi) : "l"(p));
    return make_float2(__uint_as_float(lo), __uint_as_float(hi));
}

// ============================================================================
// Kernel 1: FPS. One block/event, 512 threads, 16 pts/thread (8 packed pairs).
// Argmax: local fmax tree -> warp redux.max.u32 on float bits (d>=0 so bit
// order == value order) -> 16 partials in smem -> redux again. Ties resolved
// to the LOWEST global index via shared atomicMin among exact-bit matches
// (matches jnp.argmax). Double-buffered smem so one extra barrier suffices.
// Distance update uses packed f32x2 mul/add with identical per-lane rn
// rounding -> bit-identical to the reference's ((dx^2+dy^2)+dz^2).
// ============================================================================
#define FT 512
#define FPAIRS 8

__global__ __launch_bounds__(FT) void fps_kernel(const float* __restrict__ pos) {
    const int e = blockIdx.x;
    const float* pe = pos + (size_t)e * NP * 3;
    const int tid = threadIdx.x;
    const int lane = tid & 31;
    const int wid = tid >> 5;   // 16 warps

    __shared__ unsigned s_red[2][16];
    __shared__ unsigned s_minv[2];

    ull pxp[FPAIRS], pyp[FPAIRS], pzp[FPAIRS];
    float d[2 * FPAIRS];

    const float c0x = pe[0], c0y = pe[1], c0z = pe[2];
#pragma unroll
    for (int j = 0; j < FPAIRS; j++) {
        const int ga = tid + (2 * j) * FT;
        const int gb = tid + (2 * j + 1) * FT;
        const float ax = pe[3 * ga], ay = pe[3 * ga + 1], az = pe[3 * ga + 2];
        const float bx = pe[3 * gb], by = pe[3 * gb + 1], bz = pe[3 * gb + 2];
        pxp[j] = packf2(ax, bx);
        pyp[j] = packf2(ay, by);
        pzp[j] = packf2(az, bz);
        d[2 * j]     = dist2(ax - c0x, ay - c0y, az - c0z);
        d[2 * j + 1] = dist2(bx - c0x, by - c0y, bz - c0z);
    }

    if (tid == 0) {
        s_minv[0] = 0xFFFFFFFFu;
        s_minv[1] = 0xFFFFFFFFu;
        g_centers[(e * MP) * 3 + 0] = c0x;
        g_centers[(e * MP) * 3 + 1] = c0y;
        g_centers[(e * MP) * 3 + 2] = c0z;
    }

    for (int i = 1; i < MP; i++) {
        const int buf = i & 1;

        // local max
        float m = d[0];
#pragma unroll
        for (int t = 1; t < 2 * FPAIRS; t++) m = fmaxf(m, d[t]);
        const unsigned wmax = __reduce_max_sync(0xffffffffu, __float_as_uint(m));
        if (lane == 0) s_red[buf][wid] = wmax;
        __syncthreads();                              // BAR1
        const unsigned bmax =
            __reduce_max_sync(0xffffffffu, s_red[buf][lane & 15]);

        // lowest global index among exact-bit matches
#pragma unroll
        for (int t = 0; t < 2 * FPAIRS; t++)
            if (__float_as_uint(d[t]) == bmax)
                atomicMin(&s_minv[buf], (unsigned)(tid + t * FT));
        if (tid == 0) s_minv[buf ^ 1] = 0xFFFFFFFFu;  // reset other buffer
        __syncthreads();                              // BAR2

        const unsigned nxt = s_minv[buf];
        const float nx = __ldg(pe + 3 * nxt);
        const float ny = __ldg(pe + 3 * nxt + 1);
        const float nz = __ldg(pe + 3 * nxt + 2);
        if (tid == 0) {
            g_centers[(e * MP + i) * 3 + 0] = nx;
            g_centers[(e * MP + i) * 3 + 1] = ny;
            g_centers[(e * MP + i) * 3 + 2] = nz;
        }

        const ull ncx = pack2(-nx), ncy = pack2(-ny), ncz = pack2(-nz);
#pragma unroll
        for (int j = 0; j < FPAIRS; j++) {
            ull dx, dy, dz, qx, qy, qz, s1, s2;
            ADD2(dx, pxp[j], ncx);   // p - c  (== sub, exact)
            ADD2(dy, pyp[j], ncy);
            ADD2(dz, pzp[j], ncz);
            MUL2(qx, dx, dx);
            MUL2(qy, dy, dy);
            MUL2(qz, dz, dz);
            ADD2(s1, qx, qy);
            ADD2(s2, s1, qz);
            const float2 f = unpack2(s2);
            d[2 * j]     = fminf(d[2 * j], f.x);
            d[2 * j + 1] = fminf(d[2 * j + 1], f.y);
        }
    }
}

// ============================================================================
// Kernel 2: ball query + top-K (unchanged from R1 — ~60us, not the bottleneck)
// ============================================================================
__global__ __launch_bounds__(256) void bq_kernel(const float* __restrict__ pos) {
    __shared__ float s_d2[8][CAP];
    __shared__ int   s_idx[8][CAP];

    const int w = threadIdx.x >> 5;
    const int lane = threadIdx.x & 31;
    const int c = blockIdx.x * 8 + w;
    const int e = c >> 11;
    const float* pe = pos + (size_t)e * NP * 3;

    const float cx = g_centers[c * 3 + 0];
    const float cy = g_centers[c * 3 + 1];
    const float cz = g_centers[c * 3 + 2];

    int cnt = 0;
    const unsigned lmask = (1u << lane) - 1u;
    for (int j = lane; j < NP; j += 32) {
        const float d2v = dist2(pe[3 * j] - cx, pe[3 * j + 1] - cy, pe[3 * j + 2] - cz);
        const bool inr = (d2v <= R2F);
        const unsigned m = __ballot_sync(0xffffffffu, inr);
        if (inr) {
            const int slot = cnt + __popc(m & lmask);
            if (slot < CAP) { s_d2[w][slot] = d2v; s_idx[w][slot] = j; }
        }
        cnt += __popc(m);
    }
    const int C = (cnt < CAP) ? cnt : CAP;

    if (C <= KNN) {
        for (int k = lane; k < KNN; k += 32)
            g_nbr[c * KNN + k] = (k < C) ? s_idx[w][k] : 0;
        if (lane == 0) g_cnt[c] = C;
    } else {
        for (int s = 0; s < KNN; s++) {
            ull best = ~0ull;
            for (int t = lane; t < C; t += 32) {
                const ull key = ((ull)__float_as_uint(s_d2[w][t]) << 32) | (unsigned)t;
                best = (key < best) ? key : best;
            }
#pragma unroll
            for (int o = 16; o > 0; o >>= 1) {
                const ull other = __shfl_down_sync(0xffffffffu, best, o);
                best = (other < best) ? other : best;
            }
            best = __shfl_sync(0xffffffffu, best, 0);
            const int slot = (int)(unsigned)best;
            if (lane == 0) {
                g_nbr[c * KNN + s] = s_idx[w][slot];
                s_d2[w][slot] = BIGF;
            }
            __syncwarp();
        }
        if (lane == 0) g_cnt[c] = KNN;
    }
}

// ============================================================================
// Kernel 3: gather + MLP (35->64->64->128) + max-pool.
// Register-pressure fix vs R1: activations stay as floats; outputs computed
// in tiles (2 halves for L1, 4 quarters for L2, 2 halves for L3) with packed
// u64 accumulators, packing the activation on the fly (1 MOV). Peak regs
// ~160 < 170 cap -> no spills. No thread divergence: inactive neighbor slots
// compute on padded idx 0 and are gated to 0 before the max reduction.
// Max-pool: 3-step shfl_xor fmax (conflict degree 32 -> 4), lanes 0-3 atomic.
// ============================================================================
__global__ __launch_bounds__(128, 3) void mlp_kernel(
    const float* __restrict__ x, const float* __restrict__ pos,
    const float* __restrict__ W1, const float* __restrict__ b1,
    const float* __restrict__ W2, const float* __restrict__ b2,
    const float* __restrict__ W3, const float* __restrict__ b3,
    float* __restrict__ out)
{
    extern __shared__ float smem[];
    float* sW1 = smem;            // 2240
    float* sW2 = sW1 + 2240;      // 4096
    float* sW3 = sW2 + 4096;      // 8192
    float* sb1 = sW3 + 8192;      // 64
    float* sb2 = sb1 + 64;        // 64
    float* sb3 = sb2 + 64;        // 128
    int*   sOut = (int*)(sb3 + 128);  // 2*128

    const int tid = threadIdx.x;
    for (int i = tid; i < 2240; i += 128) sW1[i] = W1[i];
    for (int i = tid; i < 4096; i += 128) sW2[i] = W2[i];
    for (int i = tid; i < 8192; i += 128) sW3[i] = W3[i];
    if (tid < 64) { sb1[tid] = b1[tid]; sb2[tid] = b2[tid]; }
    sb3[tid] = b3[tid];
    sOut[tid] = 0;
    sOut[tid + 128] = 0;
    __syncthreads();

    const int cl = tid >> 6;
    const int n  = tid & 63;
    const int lane = tid & 31;
    const int c  = blockIdx.x * 2 + cl;
    const int e  = c >> 11;
    const bool active = (n < g_cnt[c]);
    int* sOutC = sOut + cl * 128;

    const int idx = g_nbr[c * KNN + n];      // padded (0) for inactive slots
    const int row = e * NP + idx;

    float inv[35];
    {
        const float4* xr = (const float4*)(x + (size_t)row * 32);
#pragma unroll
        for (int q = 0; q < 8; q++) {
            const float4 v = xr[q];
            inv[4 * q + 0] = v.x; inv[4 * q + 1] = v.y;
            inv[4 * q + 2] = v.z; inv[4 * q + 3] = v.w;
        }
        inv[32] = pos[row * 3 + 0] - g_centers[c * 3 + 0];
        inv[33] = pos[row * 3 + 1] - g_centers[c * 3 + 1];
        inv[34] = pos[row * 3 + 2] - g_centers[c * 3 + 2];
    }

    // ---- layer 1: 35 -> 64, two halves of 32 outputs (16 u64 acc) ----
    float h1[64];
#pragma unroll
    for (int h = 0; h < 2; h++) {
        ull acc[16];
#pragma unroll
        for (int k = 0; k < 8; k++) {
            const ulonglong2 bb = *(const ulonglong2*)(sb1 + h * 32 + 4 * k);
            acc[2 * k] = bb.x; acc[2 * k + 1] = bb.y;
        }
#pragma unroll
        for (int i = 0; i < 35; i++) {
            const ull a = pack2(inv[i]);
#pragma unroll
            for (int k = 0; k < 8; k++) {
                const ulonglong2 wv = *(const ulonglong2*)(sW1 + i * 64 + h * 32 + 4 * k);
                FMA2(acc[2 * k], a, wv.x);
                FMA2(acc[2 * k + 1], a, wv.y);
            }
        }
#pragma unroll
        for (int k = 0; k < 16; k++) {
            const float2 v = unpack2(acc[k]);
            h1[h * 32 + 2 * k]     = fmaxf(v.x, 0.f);
            h1[h * 32 + 2 * k + 1] = fmaxf(v.y, 0.f);
        }
    }

    // ---- layer 2: 64 -> 64, four quarters of 16 outputs (8 u64 acc) ----
    float h2[64];
#pragma unroll
    for (int q = 0; q < 4; q++) {
        ull acc[8];
#pragma unroll
        for (int k = 0; k < 4; k++) {
            const ulonglong2 bb = *(const ulonglong2*)(sb2 + q * 16 + 4 * k);
            acc[2 * k] = bb.x; acc[2 * k + 1] = bb.y;
        }
#pragma unroll
        for (int i = 0; i < 64; i++) {
            const ull a = pack2(h1[i]);
#pragma unroll
            for (int k = 0; k < 4; k++) {
                const ulonglong2 wv = *(const ulonglong2*)(sW2 + i * 64 + q * 16 + 4 * k);
                FMA2(acc[2 * k], a, wv.x);
                FMA2(acc[2 * k + 1], a, wv.y);
            }
        }
#pragma unroll
        for (int k = 0; k < 8; k++) {
            const float2 v = unpack2(acc[k]);
            h2[q * 16 + 2 * k]     = fmaxf(v.x, 0.f);
            h2[q * 16 + 2 * k + 1] = fmaxf(v.y, 0.f);
        }
    }

    // ---- layer 3: 64 -> 128, two halves of 64 outputs (32 u64 acc),
    //      fused max-pool: gate -> 3-step bfly fmax -> lanes 0-3 atomic ----
#pragma unroll
    for (int h = 0; h < 2; h++) {
        ull acc[32];
#pragma unroll
        for (int k = 0; k < 16; k++) {
            const ulonglong2 bb = *(const ulonglong2*)(sb3 + h * 64 + 4 * k);
            acc[2 * k] = bb.x; acc[2 * k + 1] = bb.y;
        }
#pragma unroll
        for (int i = 0; i < 64; i++) {
            const ull a = pack2(h2[i]);
#pragma unroll
            for (int k = 0; k < 16; k++) {
                const ulonglong2 wv = *(const ulonglong2*)(sW3 + i * 128 + h * 64 + 4 * k);
                FMA2(acc[2 * k], a, wv.x);
                FMA2(acc[2 * k + 1], a, wv.y);
            }
        }
#pragma unroll
        for (int k = 0; k < 32; k++) {
            const float2 v = unpack2(acc[k]);
            float v0 = active ? fmaxf(v.x, 0.f) : 0.f;
            float v1 = active ? fmaxf(v.y, 0.f) : 0.f;
#pragma unroll
            for (int o = 16; o >= 4; o >>= 1) {
                v0 = fmaxf(v0, __shfl_xor_sync(0xffffffffu, v0, o));
                v1 = fmaxf(v1, __shfl_xor_sync(0xffffffffu, v1, o));
            }
            if (lane < 4) {
                atomicMax(sOutC + h * 64 + 2 * k,     __float_as_int(v0));
                atomicMax(sOutC + h * 64 + 2 * k + 1, __float_as_int(v1));
            }
        }
    }
    __syncthreads();

    // ---- write outputs: [x_out | pos_out | batch_out] as float32 ----
    {
        int i = tid;
        int cc = blockIdx.x * 2 + (i >> 7);
        out[(size_t)cc * 128 + (i & 127)] = __int_as_float(sOut[i]);
        i = tid + 128;
        cc = blockIdx.x * 2 + (i >> 7);
        out[(size_t)cc * 128 + (i & 127)] = __int_as_float(sOut[i]);
    }
    if (tid < 6) {
        const int cc = blockIdx.x * 2 + (tid / 3);
        out[POS_OFF + (size_t)cc * 3 + (tid % 3)] = g_centers[cc * 3 + (tid % 3)];
    }
    if (tid < 2) {
        const int cc = blockIdx.x * 2 + tid;
        out[BATCH_OFF + cc] = (float)(cc >> 11);
    }
}

// ============================================================================
extern "C" void kernel_launch(void* const* d_in, const int* in_sizes, int n_in,
                              void* d_out, int out_size) {
    const float* x   = (const float*)d_in[0];
    const float* pos = (const float*)d_in[1];
    const float* W1 = (const float*)d_in[3];
    const float* b1 = (const float*)d_in[4];
    const float* W2 = (const float*)d_in[5];
    const float* b2 = (const float*)d_in[6];
    const float* W3 = (const float*)d_in[7];
    const float* b3 = (const float*)d_in[8];
    float* out = (float*)d_out;

    fps_kernel<<<B_EV, FT>>>(pos);
    bq_kernel<<<NC / 8, 256>>>(pos);

    const int smem_bytes = (2240 + 4096 + 8192 + 64 + 64 + 128 + 256) * 4; // 60160
    cudaFuncSetAttribute(mlp_kernel, cudaFuncAttributeMaxDynamicSharedMemorySize,
                         smem_bytes);
    mlp_kernel<<<NC / 2, 128, smem_bytes>>>(x, pos, W1, b1, W2, b2, W3, b3, out);
}

// round 3
// speedup vs baseline: 1.5092x; 1.2104x over previous
#include <cuda_runtime.h>
#include <cstdint>

#define B_EV 4
#define NP 8192
#define MP 2048
#define KNN 64
#define NC (B_EV * MP)
#define R2F 0.04f
#define BIGF 1e10f
#define CAP 512

#define XLEN (NC * 128)
#define POS_OFF XLEN
#define BATCH_OFF (XLEN + NC * 3)

typedef unsigned long long ull;

// ---------------- scratch ---------------------------------------------------
__device__ float g_centers[NC * 3];
__device__ int   g_nbr[NC * KNN];
__device__ int   g_cnt[NC];
__device__ float g_U[B_EV * NP * 64];   // per-point b1 + x @ W1[0:32]  (8 MB)

// Deterministic distance: no FMA contraction, ((x2+y2)+z2) order.
__device__ __forceinline__ float dist2(float dx, float dy, float dz) {
    return __fadd_rn(__fadd_rn(__fmul_rn(dx, dx), __fmul_rn(dy, dy)),
                     __fmul_rn(dz, dz));
}

// ---------------- packed f32x2 helpers (per-lane rn == scalar rn) -----------
#define FMA2(acc, a, b) \
    asm("fma.rn.f32x2 %0, %1, %2, %0;" : "+l"(acc) : "l"(a), "l"(b))
#define ADD2(dst, a, b) \
    asm("add.rn.f32x2 %0, %1, %2;" : "=l"(dst) : "l"(a), "l"(b))
#define MUL2(dst, a, b) \
    asm("mul.rn.f32x2 %0, %1, %2;" : "=l"(dst) : "l"(a), "l"(b))

__device__ __forceinline__ ull pack2(float v) {
    ull r;
    asm("mov.b64 %0, {%1, %1};" : "=l"(r) : "r"(__float_as_uint(v)));
    return r;
}
__device__ __forceinline__ ull packf2(float lo, float hi) {
    ull r;
    asm("mov.b64 %0, {%1, %2};" : "=l"(r)
        : "r"(__float_as_uint(lo)), "r"(__float_as_uint(hi)));
    return r;
}
__device__ __forceinline__ float2 unpack2(ull p) {
    unsigned lo, hi;
    asm("mov.b64 {%0, %1}, %2;" : "=r"(lo), "=r"(hi) : "l"(p));
    return make_float2(__uint_as_float(lo), __uint_as_float(hi));
}

// ============================================================================
// Kernel 1: FPS with spatial pruning.
// One block/event, 512 threads, 16 pts/thread. Prologue: counting-sort the
// 8192 points into 64 Morton cells (smem), so each thread holds 16 spatially
// compact points and each warp has a tight bbox. Per iteration a warp skips
// its whole distance update iff lb2(bbox, c) >= warp_max_d (then every d in
// the warp and the warp max are provably unchanged -> bit-exact skip; lb2 is
// deflated by 1e-6 to absorb rounding-up). Argmax ties resolved to the lowest
// ORIGINAL index via shared atomicMin among exact-bit matches (== jnp.argmax).
// All value-producing arithmetic identical to the reference order.
// ============================================================================
#define FT 512

__global__ __launch_bounds__(FT) void fps_kernel(const float* __restrict__ pos) {
    const int e = blockIdx.x;
    const float* pe = pos + (size_t)e * NP * 3;
    const int tid = threadIdx.x;
    const int lane = tid & 31;
    const int wid = tid >> 5;   // 16 warps

    extern __shared__ float sm[];
    float* sx = sm;                 // NP
    float* sy = sx + NP;
    float* sz = sy + NP;
    int*   sidx = (int*)(sz + NP);  // NP
    __shared__ int s_cnt[64];
    __shared__ unsigned s_red[16];
    __shared__ unsigned s_minv[2];

    // ---- bin by 2-bit-per-dim Morton cell (64 cells) ----
    if (tid < 64) s_cnt[tid] = 0;
    __syncthreads();

    float ox[16], oy[16], oz[16];
    int cel[16];
#pragma unroll
    for (int t = 0; t < 16; t++) {
        const int j = tid + t * FT;
        ox[t] = pe[3 * j]; oy[t] = pe[3 * j + 1]; oz[t] = pe[3 * j + 2];
        int ix = (int)(ox[t] * 4.f); ix = ix < 3 ? ix : 3;
        int iy = (int)(oy[t] * 4.f); iy = iy < 3 ? iy : 3;
        int iz = (int)(oz[t] * 4.f); iz = iz < 3 ? iz : 3;
        cel[t] = ((ix >> 1) << 5) | ((iy >> 1) << 4) | ((iz >> 1) << 3) |
                 ((ix & 1) << 2) | ((iy & 1) << 1) | (iz & 1);
        atomicAdd(&s_cnt[cel[t]], 1);
    }
    __syncthreads();
    if (tid == 0) {
        int run = 0;
        for (int c2 = 0; c2 < 64; c2++) { const int v = s_cnt[c2]; s_cnt[c2] = run; run += v; }
    }
    __syncthreads();
#pragma unroll
    for (int t = 0; t < 16; t++) {
        const int p = atomicAdd(&s_cnt[cel[t]], 1);
        sx[p] = ox[t]; sy[p] = oy[t]; sz[p] = oz[t]; sidx[p] = tid + t * FT;
    }
    __syncthreads();

    // ---- load my contiguous 16 sorted points; per-thread bbox ----
    ull pxp[8], pyp[8], pzp[8];
    int io[16];
    float d[16];
    float bnx = 2.f, bny = 2.f, bnz = 2.f, bxx = -1.f, bxy = -1.f, bxz = -1.f;
    const int base = tid * 16;
#pragma unroll
    for (int j = 0; j < 8; j++) {
        const float ax = sx[base + 2 * j],     bx = sx[base + 2 * j + 1];
        const float ay = sy[base + 2 * j],     by = sy[base + 2 * j + 1];
        const float az = sz[base + 2 * j],     bz = sz[base + 2 * j + 1];
        pxp[j] = packf2(ax, bx); pyp[j] = packf2(ay, by); pzp[j] = packf2(az, bz);
        io[2 * j] = sidx[base + 2 * j]; io[2 * j + 1] = sidx[base + 2 * j + 1];
        bnx = fminf(bnx, fminf(ax, bx)); bxx = fmaxf(bxx, fmaxf(ax, bx));
        bny = fminf(bny, fminf(ay, by)); bxy = fmaxf(bxy, fmaxf(ay, by));
        bnz = fminf(bnz, fminf(az, bz)); bxz = fmaxf(bxz, fmaxf(az, bz));
    }
    // warp bbox (coords >= 0 -> float bits order-preserving)
    const float wbnx = __uint_as_float(__reduce_min_sync(0xffffffffu, __float_as_uint(bnx)));
    const float wbny = __uint_as_float(__reduce_min_sync(0xffffffffu, __float_as_uint(bny)));
    const float wbnz = __uint_as_float(__reduce_min_sync(0xffffffffu, __float_as_uint(bnz)));
    const float wbxx = __uint_as_float(__reduce_max_sync(0xffffffffu, __float_as_uint(bxx)));
    const float wbxy = __uint_as_float(__reduce_max_sync(0xffffffffu, __float_as_uint(bxy)));
    const float wbxz = __uint_as_float(__reduce_max_sync(0xffffffffu, __float_as_uint(bxz)));

    // ---- initial d vs point 0 (exact packed chain, identical rounding) ----
    const float c0x = pe[0], c0y = pe[1], c0z = pe[2];
    {
        const ull ncx = pack2(-c0x), ncy = pack2(-c0y), ncz = pack2(-c0z);
#pragma unroll
        for (int j = 0; j < 8; j++) {
            ull dx, dy, dz, qx, qy, qz, s1, s2;
            ADD2(dx, pxp[j], ncx); ADD2(dy, pyp[j], ncy); ADD2(dz, pzp[j], ncz);
            MUL2(qx, dx, dx); MUL2(qy, dy, dy); MUL2(qz, dz, dz);
            ADD2(s1, qx, qy); ADD2(s2, s1, qz);
            const float2 f = unpack2(s2);
            d[2 * j] = f.x; d[2 * j + 1] = f.y;
        }
    }
    float m = 0.f;
#pragma unroll
    for (int t = 0; t < 16; t++) m = fmaxf(m, d[t]);
    unsigned wmaxb = __reduce_max_sync(0xffffffffu, __float_as_uint(m));
    float wmaxf = __uint_as_float(wmaxb);
    if (lane == 0) s_red[wid] = wmaxb;
    if (tid == 0) {
        s_minv[0] = 0xFFFFFFFFu; s_minv[1] = 0xFFFFFFFFu;
        g_centers[(e * MP) * 3 + 0] = c0x;
        g_centers[(e * MP) * 3 + 1] = c0y;
        g_centers[(e * MP) * 3 + 2] = c0z;
    }
    __syncthreads();

    // ---- main loop ----
    for (int i = 1; i < MP; i++) {
        const int buf = i & 1;
        const unsigned bmax = __reduce_max_sync(0xffffffffu, s_red[lane & 15]);
        if (wmaxb == bmax) {
#pragma unroll
            for (int t = 0; t < 16; t++)
                if (__float_as_uint(d[t]) == bmax)
                    atomicMin(&s_minv[buf], (unsigned)io[t]);
        }
        __syncthreads();                         // BAR A
        const unsigned nxt = s_minv[buf];
        if (tid == 0) s_minv[buf ^ 1] = 0xFFFFFFFFu;
        const float nx = __ldg(pe + 3 * nxt);
        const float ny = __ldg(pe + 3 * nxt + 1);
        const float nz = __ldg(pe + 3 * nxt + 2);
        if (tid == 0) {
            g_centers[(e * MP + i) * 3 + 0] = nx;
            g_centers[(e * MP + i) * 3 + 1] = ny;
            g_centers[(e * MP + i) * 3 + 2] = nz;
        }
        // warp-level skip test (safe under-estimate of min dist^2 to bbox)
        const float lbx = fmaxf(fmaxf(wbnx - nx, nx - wbxx), 0.f);
        const float lby = fmaxf(fmaxf(wbny - ny, ny - wbxy), 0.f);
        const float lbz = fmaxf(fmaxf(wbnz - nz, nz - wbxz), 0.f);
        const float lb2 = ((lbx * lbx + lby * lby) + lbz * lbz) * 0.999999f;

        if (lb2 < wmaxf) {
            const ull ncx = pack2(-nx), ncy = pack2(-ny), ncz = pack2(-nz);
            float mm = 0.f;
#pragma unroll
            for (int j = 0; j < 8; j++) {
                ull dx, dy, dz, qx, qy, qz, s1, s2;
                ADD2(dx, pxp[j], ncx); ADD2(dy, pyp[j], ncy); ADD2(dz, pzp[j], ncz);
                MUL2(qx, dx, dx); MUL2(qy, dy, dy); MUL2(qz, dz, dz);
                ADD2(s1, qx, qy); ADD2(s2, s1, qz);
                const float2 f = unpack2(s2);
                d[2 * j]     = fminf(d[2 * j], f.x);
                d[2 * j + 1] = fminf(d[2 * j + 1], f.y);
                mm = fmaxf(mm, fmaxf(d[2 * j], d[2 * j + 1]));
            }
            wmaxb = __reduce_max_sync(0xffffffffu, __float_as_uint(mm));
            wmaxf = __uint_as_float(wmaxb);
            if (lane == 0) s_red[wid] = wmaxb;
        }
        __syncthreads();                         // BAR B
    }
}

// ============================================================================
// Kernel 2: ball query + top-K (unchanged)
// ============================================================================
__global__ __launch_bounds__(256) void bq_kernel(const float* __restrict__ pos) {
    __shared__ float s_d2[8][CAP];
    __shared__ int   s_idx[8][CAP];

    const int w = threadIdx.x >> 5;
    const int lane = threadIdx.x & 31;
    const int c = blockIdx.x * 8 + w;
    const int e = c >> 11;
    const float* pe = pos + (size_t)e * NP * 3;

    const float cx = g_centers[c * 3 + 0];
    const float cy = g_centers[c * 3 + 1];
    const float cz = g_centers[c * 3 + 2];

    int cnt = 0;
    const unsigned lmask = (1u << lane) - 1u;
    for (int j = lane; j < NP; j += 32) {
        const float d2v = dist2(pe[3 * j] - cx, pe[3 * j + 1] - cy, pe[3 * j + 2] - cz);
        const bool inr = (d2v <= R2F);
        const unsigned mball = __ballot_sync(0xffffffffu, inr);
        if (inr) {
            const int slot = cnt + __popc(mball & lmask);
            if (slot < CAP) { s_d2[w][slot] = d2v; s_idx[w][slot] = j; }
        }
        cnt += __popc(mball);
    }
    const int C = (cnt < CAP) ? cnt : CAP;

    if (C <= KNN) {
        for (int k = lane; k < KNN; k += 32)
            g_nbr[c * KNN + k] = (k < C) ? s_idx[w][k] : 0;
        if (lane == 0) g_cnt[c] = C;
    } else {
        for (int s = 0; s < KNN; s++) {
            ull best = ~0ull;
            for (int t = lane; t < C; t += 32) {
                const ull key = ((ull)__float_as_uint(s_d2[w][t]) << 32) | (unsigned)t;
                best = (key < best) ? key : best;
            }
#pragma unroll
            for (int o = 16; o > 0; o >>= 1) {
                const ull other = __shfl_down_sync(0xffffffffu, best, o);
                best = (other < best) ? other : best;
            }
            best = __shfl_sync(0xffffffffu, best, 0);
            const int slot = (int)(unsigned)best;
            if (lane == 0) {
                g_nbr[c * KNN + s] = s_idx[w][slot];
                s_d2[w][slot] = BIGF;
            }
            __syncwarp();
        }
        if (lane == 0) g_cnt[c] = KNN;
    }
}

// ============================================================================
// Kernel 0b: per-point U = b1 + x @ W1[0:32]  (layer-1 x-part, reused ~16x).
// Summation order: init b1, accumulate i = 0..31 ascending -> identical to
// the fused order used in mlp (which appends i = 32..34).
// ============================================================================
__global__ __launch_bounds__(256) void upre_kernel(
    const float* __restrict__ x, const float* __restrict__ W1,
    const float* __restrict__ b1)
{
    __shared__ float sW[32 * 64];
    __shared__ float sb[64];
    const int tid = threadIdx.x;
    for (int i = tid; i < 2048; i += 256) sW[i] = W1[i];
    if (tid < 64) sb[tid] = b1[tid];
    __syncthreads();

    const int row = blockIdx.x * 256 + tid;
    float inv[32];
    const float4* xr = (const float4*)(x + (size_t)row * 32);
#pragma unroll
    for (int q = 0; q < 8; q++) {
        const float4 v = xr[q];
        inv[4 * q] = v.x; inv[4 * q + 1] = v.y; inv[4 * q + 2] = v.z; inv[4 * q + 3] = v.w;
    }
    float4* ur = (float4*)(g_U + (size_t)row * 64);
#pragma unroll
    for (int h = 0; h < 2; h++) {
        ull acc[16];
#pragma unroll
        for (int k = 0; k < 8; k++) {
            const ulonglong2 bb = *(const ulonglong2*)(sb + h * 32 + 4 * k);
            acc[2 * k] = bb.x; acc[2 * k + 1] = bb.y;
        }
#pragma unroll
        for (int i = 0; i < 32; i++) {
            const ull a = pack2(inv[i]);
#pragma unroll
            for (int k = 0; k < 8; k++) {
                const ulonglong2 wv = *(const ulonglong2*)(sW + i * 64 + h * 32 + 4 * k);
                FMA2(acc[2 * k], a, wv.x);
                FMA2(acc[2 * k + 1], a, wv.y);
            }
        }
#pragma unroll
        for (int k = 0; k < 8; k++) {
            const float2 v0 = unpack2(acc[2 * k]);
            const float2 v1 = unpack2(acc[2 * k + 1]);
            ur[h * 8 + k] = make_float4(v0.x, v0.y, v1.x, v1.y);
        }
    }
}

// ============================================================================
// Kernel 3: gather + MLP + max-pool. Layer 1 uses precomputed U + 3 rel rows.
// L3 re-tiled to 4x32 outputs (acc[16]) to cap live registers (~120).
// ============================================================================
__global__ __launch_bounds__(128, 3) void mlp_kernel(
    const float* __restrict__ pos,
    const float* __restrict__ W1,
    const float* __restrict__ W2, const float* __restrict__ b2,
    const float* __restrict__ W3, const float* __restrict__ b3,
    float* __restrict__ out)
{
    extern __shared__ float smem[];
    float* sW1p = smem;            // 3*64 = 192 (rows 32..34 of W1)
    float* sW2 = sW1p + 192;       // 4096
    float* sW3 = sW2 + 4096;       // 8192
    float* sb2 = sW3 + 8192;       // 64
    float* sb3 = sb2 + 64;         // 128
    int*   sOut = (int*)(sb3 + 128);  // 2*128

    const int tid = threadIdx.x;
    for (int i = tid; i < 192; i += 128) sW1p[i] = W1[2048 + i];
    for (int i = tid; i < 4096; i += 128) sW2[i] = W2[i];
    for (int i = tid; i < 8192; i += 128) sW3[i] = W3[i];
    if (tid < 64) sb2[tid] = b2[tid];
    sb3[tid] = b3[tid];
    sOut[tid] = 0;
    sOut[tid + 128] = 0;
    __syncthreads();

    const int cl = tid >> 6;
    const int n  = tid & 63;
    const int lane = tid & 31;
    const int c  = blockIdx.x * 2 + cl;
    const int e  = c >> 11;
    const bool active = (n < g_cnt[c]);
    int* sOutC = sOut + cl * 128;

    const int idx = g_nbr[c * KNN + n];
    const int row = e * NP + idx;

    float rel[3];
    rel[0] = pos[row * 3 + 0] - g_centers[c * 3 + 0];
    rel[1] = pos[row * 3 + 1] - g_centers[c * 3 + 1];
    rel[2] = pos[row * 3 + 2] - g_centers[c * 3 + 2];

    // ---- layer 1: h1 = relu(U[row] + rel @ W1[32:35]) ----
    float h1[64];
    const float4* ur = (const float4*)(g_U + (size_t)row * 64);
#pragma unroll
    for (int h = 0; h < 2; h++) {
        ull acc[16];
#pragma unroll
        for (int q = 0; q < 8; q++) {
            const float4 u = ur[h * 8 + q];
            acc[2 * q]     = packf2(u.x, u.y);
            acc[2 * q + 1] = packf2(u.z, u.w);
        }
#pragma unroll
        for (int i = 0; i < 3; i++) {
            const ull a = pack2(rel[i]);
#pragma unroll
            for (int k = 0; k < 8; k++) {
                const ulonglong2 wv = *(const ulonglong2*)(sW1p + i * 64 + h * 32 + 4 * k);
                FMA2(acc[2 * k], a, wv.x);
                FMA2(acc[2 * k + 1], a, wv.y);
            }
        }
#pragma unroll
        for (int k = 0; k < 16; k++) {
            const float2 v = unpack2(acc[k]);
            h1[h * 32 + 2 * k]     = fmaxf(v.x, 0.f);
            h1[h * 32 + 2 * k + 1] = fmaxf(v.y, 0.f);
        }
    }

    // ---- layer 2: 64 -> 64, four quarters (acc[8]) ----
    float h2[64];
#pragma unroll
    for (int q = 0; q < 4; q++) {
        ull acc[8];
#pragma unroll
        for (int k = 0; k < 4; k++) {
            const ulonglong2 bb = *(const ulonglong2*)(sb2 + q * 16 + 4 * k);
            acc[2 * k] = bb.x; acc[2 * k + 1] = bb.y;
        }
#pragma unroll
        for (int i = 0; i < 64; i++) {
            const ull a = pack2(h1[i]);
#pragma unroll
            for (int k = 0; k < 4; k++) {
                const ulonglong2 wv = *(const ulonglong2*)(sW2 + i * 64 + q * 16 + 4 * k);
                FMA2(acc[2 * k], a, wv.x);
                FMA2(acc[2 * k + 1], a, wv.y);
            }
        }
#pragma unroll
        for (int k = 0; k < 8; k++) {
            const float2 v = unpack2(acc[k]);
            h2[q * 16 + 2 * k]     = fmaxf(v.x, 0.f);
            h2[q * 16 + 2 * k + 1] = fmaxf(v.y, 0.f);
        }
    }

    // ---- layer 3: 64 -> 128, four tiles of 32 outputs, fused max-pool ----
#pragma unroll
    for (int qd = 0; qd < 4; qd++) {
        ull acc[16];
#pragma unroll
        for (int k = 0; k < 8; k++) {
            const ulonglong2 bb = *(const ulonglong2*)(sb3 + qd * 32 + 4 * k);
            acc[2 * k] = bb.x; acc[2 * k + 1] = bb.y;
        }
#pragma unroll
        for (int i = 0; i < 64; i++) {
            const ull a = pack2(h2[i]);
#pragma unroll
            for (int k = 0; k < 8; k++) {
                const ulonglong2 wv = *(const ulonglong2*)(sW3 + i * 128 + qd * 32 + 4 * k);
                FMA2(acc[2 * k], a, wv.x);
                FMA2(acc[2 * k + 1], a, wv.y);
            }
        }
#pragma unroll
        for (int k = 0; k < 16; k++) {
            const float2 v = unpack2(acc[k]);
            float v0 = active ? fmaxf(v.x, 0.f) : 0.f;
            float v1 = active ? fmaxf(v.y, 0.f) : 0.f;
#pragma unroll
            for (int o = 16; o >= 4; o >>= 1) {
                v0 = fmaxf(v0, __shfl_xor_sync(0xffffffffu, v0, o));
                v1 = fmaxf(v1, __shfl_xor_sync(0xffffffffu, v1, o));
            }
            if (lane < 4) {
                atomicMax(sOutC + qd * 32 + 2 * k,     __float_as_int(v0));
                atomicMax(sOutC + qd * 32 + 2 * k + 1, __float_as_int(v1));
            }
        }
    }
    __syncthreads();

    // ---- outputs: [x_out | pos_out | batch_out] as float32 ----
    {
        int i = tid;
        int cc = blockIdx.x * 2 + (i >> 7);
        out[(size_t)cc * 128 + (i & 127)] = __int_as_float(sOut[i]);
        i = tid + 128;
        cc = blockIdx.x * 2 + (i >> 7);
        out[(size_t)cc * 128 + (i & 127)] = __int_as_float(sOut[i]);
    }
    if (tid < 6) {
        const int cc = blockIdx.x * 2 + (tid / 3);
        out[POS_OFF + (size_t)cc * 3 + (tid % 3)] = g_centers[cc * 3 + (tid % 3)];
    }
    if (tid < 2) {
        const int cc = blockIdx.x * 2 + tid;
        out[BATCH_OFF + cc] = (float)(cc >> 11);
    }
}

// ============================================================================
extern "C" void kernel_launch(void* const* d_in, const int* in_sizes, int n_in,
                              void* d_out, int out_size) {
    const float* x   = (const float*)d_in[0];
    const float* pos = (const float*)d_in[1];
    const float* W1 = (const float*)d_in[3];
    const float* b1 = (const float*)d_in[4];
    const float* W2 = (const float*)d_in[5];
    const float* b2 = (const float*)d_in[6];
    const float* W3 = (const float*)d_in[7];
    const float* b3 = (const float*)d_in[8];
    float* out = (float*)d_out;

    const int fps_smem = (3 * NP) * 4 + NP * 4;   // 131072 B
    cudaFuncSetAttribute(fps_kernel, cudaFuncAttributeMaxDynamicSharedMemorySize,
                         fps_smem);
    fps_kernel<<<B_EV, FT, fps_smem>>>(pos);

    upre_kernel<<<(B_EV * NP) / 256, 256>>>(x, W1, b1);
    bq_kernel<<<NC / 8, 256>>>(pos);

    const int mlp_smem = (192 + 4096 + 8192 + 64 + 128 + 256) * 4;  // 51712 B
    cudaFuncSetAttribute(mlp_kernel, cudaFuncAttributeMaxDynamicSharedMemorySize,
                         mlp_smem);
    mlp_kernel<<<NC / 2, 128, mlp_smem>>>(pos, W1, W2, b2, W3, b3, out);
}

// round 4
// speedup vs baseline: 1.5111x; 1.0013x over previous
#include <cuda_runtime.h>
#include <cstdint>

#define B_EV 4
#define NP 8192
#define MP 2048
#define KNN 64
#define NC (B_EV * MP)
#define R2F 0.04f
#define BIGF 1e10f
#define CAP 512

#define XLEN (NC * 128)
#define POS_OFF XLEN
#define BATCH_OFF (XLEN + NC * 3)

typedef unsigned long long ull;

// ---------------- scratch ---------------------------------------------------
__device__ float g_centers[NC * 3];
__device__ int   g_nbr[NC * KNN];
__device__ int   g_cnt[NC];
__device__ float g_U[B_EV * NP * 64];   // per-point b1 + x @ W1[0:32]  (8 MB)

// Deterministic distance: no FMA contraction, ((x2+y2)+z2) order.
__device__ __forceinline__ float dist2(float dx, float dy, float dz) {
    return __fadd_rn(__fadd_rn(__fmul_rn(dx, dx), __fmul_rn(dy, dy)),
                     __fmul_rn(dz, dz));
}

// ---------------- packed f32x2 helpers (per-lane rn == scalar rn) -----------
#define FMA2(acc, a, b) \
    asm("fma.rn.f32x2 %0, %1, %2, %0;" : "+l"(acc) : "l"(a), "l"(b))
#define ADD2(dst, a, b) \
    asm("add.rn.f32x2 %0, %1, %2;" : "=l"(dst) : "l"(a), "l"(b))
#define MUL2(dst, a, b) \
    asm("mul.rn.f32x2 %0, %1, %2;" : "=l"(dst) : "l"(a), "l"(b))

__device__ __forceinline__ ull pack2(float v) {
    ull r;
    asm("mov.b64 %0, {%1, %1};" : "=l"(r) : "r"(__float_as_uint(v)));
    return r;
}
__device__ __forceinline__ ull packf2(float lo, float hi) {
    ull r;
    asm("mov.b64 %0, {%1, %2};" : "=l"(r)
        : "r"(__float_as_uint(lo)), "r"(__float_as_uint(hi)));
    return r;
}
__device__ __forceinline__ float2 unpack2(ull p) {
    unsigned lo, hi;
    asm("mov.b64 {%0, %1}, %2;" : "=r"(lo), "=r"(hi) : "l"(p));
    return make_float2(__uint_as_float(lo), __uint_as_float(hi));
}

// ============================================================================
// Kernel 1: FPS with spatial pruning.
// One block/event, 512 threads, 16 pts/thread. Prologue: counting-sort the
// 8192 points into 64 Morton cells (smem), so each thread holds 16 spatially
// compact points and each warp has a tight bbox. Per iteration a warp skips
// its whole distance update iff lb2(bbox, c) >= warp_max_d (then every d in
// the warp and the warp max are provably unchanged -> bit-exact skip; lb2 is
// deflated by 1e-6 to absorb rounding-up). Argmax ties resolved to the lowest
// ORIGINAL index via shared atomicMin among exact-bit matches (== jnp.argmax).
// All value-producing arithmetic identical to the reference order.
// ============================================================================
#define FT 512

__global__ __launch_bounds__(FT) void fps_kernel(const float* __restrict__ pos) {
    const int e = blockIdx.x;
    const float* pe = pos + (size_t)e * NP * 3;
    const int tid = threadIdx.x;
    const int lane = tid & 31;
    const int wid = tid >> 5;   // 16 warps

    extern __shared__ float sm[];
    float* sx = sm;                 // NP
    float* sy = sx + NP;
    float* sz = sy + NP;
    int*   sidx = (int*)(sz + NP);  // NP
    __shared__ int s_cnt[64];
    __shared__ unsigned s_red[16];
    __shared__ unsigned s_minv[2];

    // ---- bin by 2-bit-per-dim Morton cell (64 cells) ----
    if (tid < 64) s_cnt[tid] = 0;
    __syncthreads();

    float ox[16], oy[16], oz[16];
    int cel[16];
#pragma unroll
    for (int t = 0; t < 16; t++) {
        const int j = tid + t * FT;
        ox[t] = pe[3 * j]; oy[t] = pe[3 * j + 1]; oz[t] = pe[3 * j + 2];
        int ix = (int)(ox[t] * 4.f); ix = ix < 3 ? ix : 3;
        int iy = (int)(oy[t] * 4.f); iy = iy < 3 ? iy : 3;
        int iz = (int)(oz[t] * 4.f); iz = iz < 3 ? iz : 3;
        cel[t] = ((ix >> 1) << 5) | ((iy >> 1) << 4) | ((iz >> 1) << 3) |
                 ((ix & 1) << 2) | ((iy & 1) << 1) | (iz & 1);
        atomicAdd(&s_cnt[cel[t]], 1);
    }
    __syncthreads();
    if (tid == 0) {
        int run = 0;
        for (int c2 = 0; c2 < 64; c2++) { const int v = s_cnt[c2]; s_cnt[c2] = run; run += v; }
    }
    __syncthreads();
#pragma unroll
    for (int t = 0; t < 16; t++) {
        const int p = atomicAdd(&s_cnt[cel[t]], 1);
        sx[p] = ox[t]; sy[p] = oy[t]; sz[p] = oz[t]; sidx[p] = tid + t * FT;
    }
    __syncthreads();

    // ---- load my contiguous 16 sorted points; per-thread bbox ----
    ull pxp[8], pyp[8], pzp[8];
    int io[16];
    float d[16];
    float bnx = 2.f, bny = 2.f, bnz = 2.f, bxx = -1.f, bxy = -1.f, bxz = -1.f;
    const int base = tid * 16;
#pragma unroll
    for (int j = 0; j < 8; j++) {
        const float ax = sx[base + 2 * j],     bx = sx[base + 2 * j + 1];
        const float ay = sy[base + 2 * j],     by = sy[base + 2 * j + 1];
        const float az = sz[base + 2 * j],     bz = sz[base + 2 * j + 1];
        pxp[j] = packf2(ax, bx); pyp[j] = packf2(ay, by); pzp[j] = packf2(az, bz);
        io[2 * j] = sidx[base + 2 * j]; io[2 * j + 1] = sidx[base + 2 * j + 1];
        bnx = fminf(bnx, fminf(ax, bx)); bxx = fmaxf(bxx, fmaxf(ax, bx));
        bny = fminf(bny, fminf(ay, by)); bxy = fmaxf(bxy, fmaxf(ay, by));
        bnz = fminf(bnz, fminf(az, bz)); bxz = fmaxf(bxz, fmaxf(az, bz));
    }
    // warp bbox (coords >= 0 -> float bits order-preserving)
    const float wbnx = __uint_as_float(__reduce_min_sync(0xffffffffu, __float_as_uint(bnx)));
    const float wbny = __uint_as_float(__reduce_min_sync(0xffffffffu, __float_as_uint(bny)));
    const float wbnz = __uint_as_float(__reduce_min_sync(0xffffffffu, __float_as_uint(bnz)));
    const float wbxx = __uint_as_float(__reduce_max_sync(0xffffffffu, __float_as_uint(bxx)));
    const float wbxy = __uint_as_float(__reduce_max_sync(0xffffffffu, __float_as_uint(bxy)));
    const float wbxz = __uint_as_float(__reduce_max_sync(0xffffffffu, __float_as_uint(bxz)));

    // ---- initial d vs point 0 (exact packed chain, identical rounding) ----
    const float c0x = pe[0], c0y = pe[1], c0z = pe[2];
    {
        const ull ncx = pack2(-c0x), ncy = pack2(-c0y), ncz = pack2(-c0z);
#pragma unroll
        for (int j = 0; j < 8; j++) {
            ull dx, dy, dz, qx, qy, qz, s1, s2;
            ADD2(dx, pxp[j], ncx); ADD2(dy, pyp[j], ncy); ADD2(dz, pzp[j], ncz);
            MUL2(qx, dx, dx); MUL2(qy, dy, dy); MUL2(qz, dz, dz);
            ADD2(s1, qx, qy); ADD2(s2, s1, qz);
            const float2 f = unpack2(s2);
            d[2 * j] = f.x; d[2 * j + 1] = f.y;
        }
    }
    float m = 0.f;
#pragma unroll
    for (int t = 0; t < 16; t++) m = fmaxf(m, d[t]);
    unsigned wmaxb = __reduce_max_sync(0xffffffffu, __float_as_uint(m));
    float wmaxf = __uint_as_float(wmaxb);
    if (lane == 0) s_red[wid] = wmaxb;
    if (tid == 0) {
        s_minv[0] = 0xFFFFFFFFu; s_minv[1] = 0xFFFFFFFFu;
        g_centers[(e * MP) * 3 + 0] = c0x;
        g_centers[(e * MP) * 3 + 1] = c0y;
        g_centers[(e * MP) * 3 + 2] = c0z;
    }
    __syncthreads();

    // ---- main loop ----
    for (int i = 1; i < MP; i++) {
        const int buf = i & 1;
        const unsigned bmax = __reduce_max_sync(0xffffffffu, s_red[lane & 15]);
        if (wmaxb == bmax) {
#pragma unroll
            for (int t = 0; t < 16; t++)
                if (__float_as_uint(d[t]) == bmax)
                    atomicMin(&s_minv[buf], (unsigned)io[t]);
        }
        __syncthreads();                         // BAR A
        const unsigned nxt = s_minv[buf];
        if (tid == 0) s_minv[buf ^ 1] = 0xFFFFFFFFu;
        const float nx = __ldg(pe + 3 * nxt);
        const float ny = __ldg(pe + 3 * nxt + 1);
        const float nz = __ldg(pe + 3 * nxt + 2);
        if (tid == 0) {
            g_centers[(e * MP + i) * 3 + 0] = nx;
            g_centers[(e * MP + i) * 3 + 1] = ny;
            g_centers[(e * MP + i) * 3 + 2] = nz;
        }
        // warp-level skip test (safe under-estimate of min dist^2 to bbox)
        const float lbx = fmaxf(fmaxf(wbnx - nx, nx - wbxx), 0.f);
        const float lby = fmaxf(fmaxf(wbny - ny, ny - wbxy), 0.f);
        const float lbz = fmaxf(fmaxf(wbnz - nz, nz - wbxz), 0.f);
        const float lb2 = ((lbx * lbx + lby * lby) + lbz * lbz) * 0.999999f;

        if (lb2 < wmaxf) {
            const ull ncx = pack2(-nx), ncy = pack2(-ny), ncz = pack2(-nz);
            float mm = 0.f;
#pragma unroll
            for (int j = 0; j < 8; j++) {
                ull dx, dy, dz, qx, qy, qz, s1, s2;
                ADD2(dx, pxp[j], ncx); ADD2(dy, pyp[j], ncy); ADD2(dz, pzp[j], ncz);
                MUL2(qx, dx, dx); MUL2(qy, dy, dy); MUL2(qz, dz, dz);
                ADD2(s1, qx, qy); ADD2(s2, s1, qz);
                const float2 f = unpack2(s2);
                d[2 * j]     = fminf(d[2 * j], f.x);
                d[2 * j + 1] = fminf(d[2 * j + 1], f.y);
                mm = fmaxf(mm, fmaxf(d[2 * j], d[2 * j + 1]));
            }
            wmaxb = __reduce_max_sync(0xffffffffu, __float_as_uint(mm));
            wmaxf = __uint_as_float(wmaxb);
            if (lane == 0) s_red[wid] = wmaxb;
        }
        __syncthreads();                         // BAR B
    }
}

// ============================================================================
// Kernel 2: ball query + top-K (unchanged)
// ============================================================================
__global__ __launch_bounds__(256) void bq_kernel(const float* __restrict__ pos) {
    __shared__ float s_d2[8][CAP];
    __shared__ int   s_idx[8][CAP];

    const int w = threadIdx.x >> 5;
    const int lane = threadIdx.x & 31;
    const int c = blockIdx.x * 8 + w;
    const int e = c >> 11;
    const float* pe = pos + (size_t)e * NP * 3;

    const float cx = g_centers[c * 3 + 0];
    const float cy = g_centers[c * 3 + 1];
    const float cz = g_centers[c * 3 + 2];

    int cnt = 0;
    const unsigned lmask = (1u << lane) - 1u;
    for (int j = lane; j < NP; j += 32) {
        const float d2v = dist2(pe[3 * j] - cx, pe[3 * j + 1] - cy, pe[3 * j + 2] - cz);
        const bool inr = (d2v <= R2F);
        const unsigned mball = __ballot_sync(0xffffffffu, inr);
        if (inr) {
            const int slot = cnt + __popc(mball & lmask);
            if (slot < CAP) { s_d2[w][slot] = d2v; s_idx[w][slot] = j; }
        }
        cnt += __popc(mball);
    }
    const int C = (cnt < CAP) ? cnt : CAP;

    if (C <= KNN) {
        for (int k = lane; k < KNN; k += 32)
            g_nbr[c * KNN + k] = (k < C) ? s_idx[w][k] : 0;
        if (lane == 0) g_cnt[c] = C;
    } else {
        for (int s = 0; s < KNN; s++) {
            ull best = ~0ull;
            for (int t = lane; t < C; t += 32) {
                const ull key = ((ull)__float_as_uint(s_d2[w][t]) << 32) | (unsigned)t;
                best = (key < best) ? key : best;
            }
#pragma unroll
            for (int o = 16; o > 0; o >>= 1) {
                const ull other = __shfl_down_sync(0xffffffffu, best, o);
                best = (other < best) ? other : best;
            }
            best = __shfl_sync(0xffffffffu, best, 0);
            const int slot = (int)(unsigned)best;
            if (lane == 0) {
                g_nbr[c * KNN + s] = s_idx[w][slot];
                s_d2[w][slot] = BIGF;
            }
            __syncwarp();
        }
        if (lane == 0) g_cnt[c] = KNN;
    }
}

// ============================================================================
// Kernel 0b: per-point U = b1 + x @ W1[0:32]  (layer-1 x-part, reused ~16x).
// Summation order: init b1, accumulate i = 0..31 ascending -> identical to
// the fused order used in mlp (which appends i = 32..34).
// ============================================================================
__global__ __launch_bounds__(256) void upre_kernel(
    const float* __restrict__ x, const float* __restrict__ W1,
    const float* __restrict__ b1)
{
    __shared__ float sW[32 * 64];
    __shared__ float sb[64];
    const int tid = threadIdx.x;
    for (int i = tid; i < 2048; i += 256) sW[i] = W1[i];
    if (tid < 64) sb[tid] = b1[tid];
    __syncthreads();

    const int row = blockIdx.x * 256 + tid;
    float inv[32];
    const float4* xr = (const float4*)(x + (size_t)row * 32);
#pragma unroll
    for (int q = 0; q < 8; q++) {
        const float4 v = xr[q];
        inv[4 * q] = v.x; inv[4 * q + 1] = v.y; inv[4 * q + 2] = v.z; inv[4 * q + 3] = v.w;
    }
    float4* ur = (float4*)(g_U + (size_t)row * 64);
#pragma unroll
    for (int h = 0; h < 2; h++) {
        ull acc[16];
#pragma unroll
        for (int k = 0; k < 8; k++) {
            const ulonglong2 bb = *(const ulonglong2*)(sb + h * 32 + 4 * k);
            acc[2 * k] = bb.x; acc[2 * k + 1] = bb.y;
        }
#pragma unroll
        for (int i = 0; i < 32; i++) {
            const ull a = pack2(inv[i]);
#pragma unroll
            for (int k = 0; k < 8; k++) {
                const ulonglong2 wv = *(const ulonglong2*)(sW + i * 64 + h * 32 + 4 * k);
                FMA2(acc[2 * k], a, wv.x);
                FMA2(acc[2 * k + 1], a, wv.y);
            }
        }
#pragma unroll
        for (int k = 0; k < 8; k++) {
            const float2 v0 = unpack2(acc[2 * k]);
            const float2 v1 = unpack2(acc[2 * k + 1]);
            ur[h * 8 + k] = make_float4(v0.x, v0.y, v1.x, v1.y);
        }
    }
}

// ============================================================================
// Kernel 3: gather + MLP + max-pool. Layer 1 uses precomputed U + 3 rel rows.
// L3 re-tiled to 4x32 outputs (acc[16]) to cap live registers (~120).
// ============================================================================
__global__ __launch_bounds__(128, 3) void mlp_kernel(
    const float* __restrict__ pos,
    const float* __restrict__ W1,
    const float* __restrict__ W2, const float* __restrict__ b2,
    const float* __restrict__ W3, const float* __restrict__ b3,
    float* __restrict__ out)
{
    extern __shared__ float smem[];
    float* sW1p = smem;            // 3*64 = 192 (rows 32..34 of W1)
    float* sW2 = sW1p + 192;       // 4096
    float* sW3 = sW2 + 4096;       // 8192
    float* sb2 = sW3 + 8192;       // 64
    float* sb3 = sb2 + 64;         // 128
    int*   sOut = (int*)(sb3 + 128);  // 2*128

    const int tid = threadIdx.x;
    for (int i = tid; i < 192; i += 128) sW1p[i] = W1[2048 + i];
    for (int i = tid; i < 4096; i += 128) sW2[i] = W2[i];
    for (int i = tid; i < 8192; i += 128) sW3[i] = W3[i];
    if (tid < 64) sb2[tid] = b2[tid];
    sb3[tid] = b3[tid];
    sOut[tid] = 0;
    sOut[tid + 128] = 0;
    __syncthreads();

    const int cl = tid >> 6;
    const int n  = tid & 63;
    const int lane = tid & 31;
    const int c  = blockIdx.x * 2 + cl;
    const int e  = c >> 11;
    const bool active = (n < g_cnt[c]);
    int* sOutC = sOut + cl * 128;

    const int idx = g_nbr[c * KNN + n];
    const int row = e * NP + idx;

    float rel[3];
    rel[0] = pos[row * 3 + 0] - g_centers[c * 3 + 0];
    rel[1] = pos[row * 3 + 1] - g_centers[c * 3 + 1];
    rel[2] = pos[row * 3 + 2] - g_centers[c * 3 + 2];

    // ---- layer 1: h1 = relu(U[row] + rel @ W1[32:35]) ----
    float h1[64];
    const float4* ur = (const float4*)(g_U + (size_t)row * 64);
#pragma unroll
    for (int h = 0; h < 2; h++) {
        ull acc[16];
#pragma unroll
        for (int q = 0; q < 8; q++) {
            const float4 u = ur[h * 8 + q];
            acc[2 * q]     = packf2(u.x, u.y);
            acc[2 * q + 1] = packf2(u.z, u.w);
        }
#pragma unroll
        for (int i = 0; i < 3; i++) {
            const ull a = pack2(rel[i]);
#pragma unroll
            for (int k = 0; k < 8; k++) {
                const ulonglong2 wv = *(const ulonglong2*)(sW1p + i * 64 + h * 32 + 4 * k);
                FMA2(acc[2 * k], a, wv.x);
                FMA2(acc[2 * k + 1], a, wv.y);
            }
        }
#pragma unroll
        for (int k = 0; k < 16; k++) {
            const float2 v = unpack2(acc[k]);
            h1[h * 32 + 2 * k]     = fmaxf(v.x, 0.f);
            h1[h * 32 + 2 * k + 1] = fmaxf(v.y, 0.f);
        }
    }

    // ---- layer 2: 64 -> 64, four quarters (acc[8]) ----
    float h2[64];
#pragma unroll
    for (int q = 0; q < 4; q++) {
        ull acc[8];
#pragma unroll
        for (int k = 0; k < 4; k++) {
            const ulonglong2 bb = *(const ulonglong2*)(sb2 + q * 16 + 4 * k);
            acc[2 * k] = bb.x; acc[2 * k + 1] = bb.y;
        }
#pragma unroll
        for (int i = 0; i < 64; i++) {
            const ull a = pack2(h1[i]);
#pragma unroll
            for (int k = 0; k < 4; k++) {
                const ulonglong2 wv = *(const ulonglong2*)(sW2 + i * 64 + q * 16 + 4 * k);
                FMA2(acc[2 * k], a, wv.x);
                FMA2(acc[2 * k + 1], a, wv.y);
            }
        }
#pragma unroll
        for (int k = 0; k < 8; k++) {
            const float2 v = unpack2(acc[k]);
            h2[q * 16 + 2 * k]     = fmaxf(v.x, 0.f);
            h2[q * 16 + 2 * k + 1] = fmaxf(v.y, 0.f);
        }
    }

    // ---- layer 3: 64 -> 128, four tiles of 32 outputs, fused max-pool ----
#pragma unroll
    for (int qd = 0; qd < 4; qd++) {
        ull acc[16];
#pragma unroll
        for (int k = 0; k < 8; k++) {
            const ulonglong2 bb = *(const ulonglong2*)(sb3 + qd * 32 + 4 * k);
            acc[2 * k] = bb.x; acc[2 * k + 1] = bb.y;
        }
#pragma unroll
        for (int i = 0; i < 64; i++) {
            const ull a = pack2(h2[i]);
#pragma unroll
            for (int k = 0; k < 8; k++) {
                const ulonglong2 wv = *(const ulonglong2*)(sW3 + i * 128 + qd * 32 + 4 * k);
                FMA2(acc[2 * k], a, wv.x);
                FMA2(acc[2 * k + 1], a, wv.y);
            }
        }
#pragma unroll
        for (int k = 0; k < 16; k++) {
            const float2 v = unpack2(acc[k]);
            float v0 = active ? fmaxf(v.x, 0.f) : 0.f;
            float v1 = active ? fmaxf(v.y, 0.f) : 0.f;
#pragma unroll
            for (int o = 16; o >= 4; o >>= 1) {
                v0 = fmaxf(v0, __shfl_xor_sync(0xffffffffu, v0, o));
                v1 = fmaxf(v1, __shfl_xor_sync(0xffffffffu, v1, o));
            }
            if (lane < 4) {
                atomicMax(sOutC + qd * 32 + 2 * k,     __float_as_int(v0));
                atomicMax(sOutC + qd * 32 + 2 * k + 1, __float_as_int(v1));
            }
        }
    }
    __syncthreads();

    // ---- outputs: [x_out | pos_out | batch_out] as float32 ----
    {
        int i = tid;
        int cc = blockIdx.x * 2 + (i >> 7);
        out[(size_t)cc * 128 + (i & 127)] = __int_as_float(sOut[i]);
        i = tid + 128;
        cc = blockIdx.x * 2 + (i >> 7);
        out[(size_t)cc * 128 + (i & 127)] = __int_as_float(sOut[i]);
    }
    if (tid < 6) {
        const int cc = blockIdx.x * 2 + (tid / 3);
        out[POS_OFF + (size_t)cc * 3 + (tid % 3)] = g_centers[cc * 3 + (tid % 3)];
    }
    if (tid < 2) {
        const int cc = blockIdx.x * 2 + tid;
        out[BATCH_OFF + cc] = (float)(cc >> 11);
    }
}

// ============================================================================
extern "C" void kernel_launch(void* const* d_in, const int* in_sizes, int n_in,
                              void* d_out, int out_size) {
    const float* x   = (const float*)d_in[0];
    const float* pos = (const float*)d_in[1];
    const float* W1 = (const float*)d_in[3];
    const float* b1 = (const float*)d_in[4];
    const float* W2 = (const float*)d_in[5];
    const float* b2 = (const float*)d_in[6];
    const float* W3 = (const float*)d_in[7];
    const float* b3 = (const float*)d_in[8];
    float* out = (float*)d_out;

    const int fps_smem = (3 * NP) * 4 + NP * 4;   // 131072 B
    cudaFuncSetAttribute(fps_kernel, cudaFuncAttributeMaxDynamicSharedMemorySize,
                         fps_smem);
    fps_kernel<<<B_EV, FT, fps_smem>>>(pos);

    upre_kernel<<<(B_EV * NP) / 256, 256>>>(x, W1, b1);
    bq_kernel<<<NC / 8, 256>>>(pos);

    const int mlp_smem = (192 + 4096 + 8192 + 64 + 128 + 256) * 4;  // 51712 B
    cudaFuncSetAttribute(mlp_kernel, cudaFuncAttributeMaxDynamicSharedMemorySize,
                         mlp_smem);
    mlp_kernel<<<NC / 2, 128, mlp_smem>>>(pos, W1, W2, b2, W3, b3, out);
}

// round 5
// speedup vs baseline: 2.0639x; 1.3658x over previous
#include <cuda_runtime.h>
#include <cstdint>

#define B_EV 4
#define NP 8192
#define MP 2048
#define KNN 64
#define NC (B_EV * MP)
#define R2F 0.04f
#define BIGF 1e10f
#define CAP 512

#define XLEN (NC * 128)
#define POS_OFF XLEN
#define BATCH_OFF (XLEN + NC * 3)

typedef unsigned long long ull;

__device__ float g_centers[NC * 3];
__device__ int   g_nbr[NC * KNN];
__device__ int   g_cnt[NC];
__device__ float g_U[B_EV * NP * 64];

__device__ __forceinline__ float dist2(float dx, float dy, float dz) {
    return __fadd_rn(__fadd_rn(__fmul_rn(dx, dx), __fmul_rn(dy, dy)),
                     __fmul_rn(dz, dz));
}

#define FMA2(acc, a, b) \
    asm("fma.rn.f32x2 %0, %1, %2, %0;" : "+l"(acc) : "l"(a), "l"(b))
#define ADD2(dst, a, b) \
    asm("add.rn.f32x2 %0, %1, %2;" : "=l"(dst) : "l"(a), "l"(b))
#define MUL2(dst, a, b) \
    asm("mul.rn.f32x2 %0, %1, %2;" : "=l"(dst) : "l"(a), "l"(b))

__device__ __forceinline__ ull pack2(float v) {
    ull r; asm("mov.b64 %0, {%1, %1};" : "=l"(r) : "r"(__float_as_uint(v)));
    return r;
}
__device__ __forceinline__ ull packf2(float lo, float hi) {
    ull r; asm("mov.b64 %0, {%1, %2};" : "=l"(r)
        : "r"(__float_as_uint(lo)), "r"(__float_as_uint(hi)));
    return r;
}
__device__ __forceinline__ float2 unpack2(ull p) {
    unsigned lo, hi; asm("mov.b64 {%0, %1}, %2;" : "=r"(lo), "=r"(hi) : "l"(p));
    return make_float2(__uint_as_float(lo), __uint_as_float(hi));
}

// ============================================================================
// Kernel 1: FPS. 512 threads x 16 pts, Morton counting-sort, warp bbox skip.
// One barrier/iter; selection = two redux.max over double-buffered per-warp
// keys (d_bits<<32 | ~orig_idx)  ->  max d, ties to lowest original index.
// Next-center coords read from a shared orig-indexed copy (no gmem on chain).
// All d-values follow the exact reference rounding chain (rel_err must be 0).
// ============================================================================
#define FT 512

__global__ __launch_bounds__(FT) void fps_kernel(const float* __restrict__ pos) {
    const int e = blockIdx.x;
    const float* pe = pos + (size_t)e * NP * 3;
    const int tid = threadIdx.x;
    const int lane = tid & 31;
    const int wid = tid >> 5;

    extern __shared__ float sm[];
    float* sx = sm;                 // sorted, later orig-indexed x
    float* sy = sx + NP;
    float* sz = sy + NP;
    int*   sidx = (int*)(sz + NP);
    __shared__ int s_cnt[64];
    __shared__ ull s_key[2][16];

    if (tid < 64) s_cnt[tid] = 0;
    __syncthreads();

    float ox[16], oy[16], oz[16];
    int cel[16];
#pragma unroll
    for (int t = 0; t < 16; t++) {
        const int j = tid + t * FT;
        ox[t] = pe[3 * j]; oy[t] = pe[3 * j + 1]; oz[t] = pe[3 * j + 2];
        int ix = (int)(ox[t] * 4.f); ix = ix < 3 ? ix : 3;
        int iy = (int)(oy[t] * 4.f); iy = iy < 3 ? iy : 3;
        int iz = (int)(oz[t] * 4.f); iz = iz < 3 ? iz : 3;
        cel[t] = ((ix >> 1) << 5) | ((iy >> 1) << 4) | ((iz >> 1) << 3) |
                 ((ix & 1) << 2) | ((iy & 1) << 1) | (iz & 1);
        atomicAdd(&s_cnt[cel[t]], 1);
    }
    __syncthreads();
    if (tid == 0) {
        int run = 0;
        for (int c2 = 0; c2 < 64; c2++) { const int v = s_cnt[c2]; s_cnt[c2] = run; run += v; }
    }
    __syncthreads();
#pragma unroll
    for (int t = 0; t < 16; t++) {
        const int p = atomicAdd(&s_cnt[cel[t]], 1);
        sx[p] = ox[t]; sy[p] = oy[t]; sz[p] = oz[t]; sidx[p] = tid + t * FT;
    }
    __syncthreads();

    ull pxp[8], pyp[8], pzp[8];
    int io[16];
    float d[16];
    float bnx = 2.f, bny = 2.f, bnz = 2.f, bxx = -1.f, bxy = -1.f, bxz = -1.f;
    const int base = tid * 16;
#pragma unroll
    for (int j = 0; j < 8; j++) {
        const float ax = sx[base + 2 * j], bx = sx[base + 2 * j + 1];
        const float ay = sy[base + 2 * j], by = sy[base + 2 * j + 1];
        const float az = sz[base + 2 * j], bz = sz[base + 2 * j + 1];
        pxp[j] = packf2(ax, bx); pyp[j] = packf2(ay, by); pzp[j] = packf2(az, bz);
        io[2 * j] = sidx[base + 2 * j]; io[2 * j + 1] = sidx[base + 2 * j + 1];
        bnx = fminf(bnx, fminf(ax, bx)); bxx = fmaxf(bxx, fmaxf(ax, bx));
        bny = fminf(bny, fminf(ay, by)); bxy = fmaxf(bxy, fmaxf(ay, by));
        bnz = fminf(bnz, fminf(az, bz)); bxz = fmaxf(bxz, fmaxf(az, bz));
    }
    const float wbnx = __uint_as_float(__reduce_min_sync(0xffffffffu, __float_as_uint(bnx)));
    const float wbny = __uint_as_float(__reduce_min_sync(0xffffffffu, __float_as_uint(bny)));
    const float wbnz = __uint_as_float(__reduce_min_sync(0xffffffffu, __float_as_uint(bnz)));
    const float wbxx = __uint_as_float(__reduce_max_sync(0xffffffffu, __float_as_uint(bxx)));
    const float wbxy = __uint_as_float(__reduce_max_sync(0xffffffffu, __float_as_uint(bxy)));
    const float wbxz = __uint_as_float(__reduce_max_sync(0xffffffffu, __float_as_uint(bxz)));
    __syncthreads();   // sorted reads done -> safe to repurpose buffers

    // orig-indexed position copy for O(LDS) next-center lookup
#pragma unroll
    for (int t = 0; t < 16; t++) {
        const int j = tid + t * FT;
        sx[j] = ox[t]; sy[j] = oy[t]; sz[j] = oz[t];
    }

    // initial d vs point 0 (exact packed chain) + first key into buffer 0
    const float c0x = pe[0], c0y = pe[1], c0z = pe[2];
    {
        const ull ncx = pack2(-c0x), ncy = pack2(-c0y), ncz = pack2(-c0z);
#pragma unroll
        for (int j = 0; j < 8; j++) {
            ull dx, dy, dz, qx, qy, qz, s1, s2;
            ADD2(dx, pxp[j], ncx); ADD2(dy, pyp[j], ncy); ADD2(dz, pzp[j], ncz);
            MUL2(qx, dx, dx); MUL2(qy, dy, dy); MUL2(qz, dz, dz);
            ADD2(s1, qx, qy); ADD2(s2, s1, qz);
            const float2 f = unpack2(s2);
            d[2 * j] = f.x; d[2 * j + 1] = f.y;
        }
    }
    ull mykey;
    float wmaxf;
    {
        float mm = d[0];
#pragma unroll
        for (int t = 1; t < 16; t++) mm = fmaxf(mm, d[t]);
        const unsigned wb = __reduce_max_sync(0xffffffffu, __float_as_uint(mm));
        unsigned cl = 0;
#pragma unroll
        for (int t = 0; t < 16; t++)
            if (__float_as_uint(d[t]) == wb) cl = max(cl, ~(unsigned)io[t]);
        const unsigned wl = __reduce_max_sync(0xffffffffu, cl);
        mykey = ((ull)wb << 32) | wl;
        wmaxf = __uint_as_float(wb);
    }
    if (lane == 0) s_key[0][wid] = mykey;
    if (tid == 0) {
        g_centers[(e * MP) * 3 + 0] = c0x;
        g_centers[(e * MP) * 3 + 1] = c0y;
        g_centers[(e * MP) * 3 + 2] = c0z;
    }

    for (int i = 1; i < MP; i++) {
        __syncthreads();   // keys for iter i-1 and (i==1) pos copy visible
        const ull kk = s_key[(i - 1) & 1][lane & 15];
        const unsigned hi = (unsigned)(kk >> 32);
        const unsigned lo = (unsigned)kk;
        const unsigned mhi = __reduce_max_sync(0xffffffffu, hi);
        const unsigned mlo = __reduce_max_sync(0xffffffffu, (hi == mhi) ? lo : 0u);
        const int nxt = (int)(~mlo);

        const float nx = sx[nxt], ny = sy[nxt], nz = sz[nxt];
        if (tid == 0) {
            g_centers[(e * MP + i) * 3 + 0] = nx;
            g_centers[(e * MP + i) * 3 + 1] = ny;
            g_centers[(e * MP + i) * 3 + 2] = nz;
        }

        const float lbx = fmaxf(fmaxf(wbnx - nx, nx - wbxx), 0.f);
        const float lby = fmaxf(fmaxf(wbny - ny, ny - wbxy), 0.f);
        const float lbz = fmaxf(fmaxf(wbnz - nz, nz - wbxz), 0.f);
        const float lb2 = ((lbx * lbx + lby * lby) + lbz * lbz) * 0.999999f;

        if (lb2 < wmaxf) {
            const ull ncx = pack2(-nx), ncy = pack2(-ny), ncz = pack2(-nz);
            float mm = 0.f;
#pragma unroll
            for (int j = 0; j < 8; j++) {
                ull dx, dy, dz, qx, qy, qz, s1, s2;
                ADD2(dx, pxp[j], ncx); ADD2(dy, pyp[j], ncy); ADD2(dz, pzp[j], ncz);
                MUL2(qx, dx, dx); MUL2(qy, dy, dy); MUL2(qz, dz, dz);
                ADD2(s1, qx, qy); ADD2(s2, s1, qz);
                const float2 f = unpack2(s2);
                d[2 * j]     = fminf(d[2 * j], f.x);
                d[2 * j + 1] = fminf(d[2 * j + 1], f.y);
                mm = fmaxf(mm, fmaxf(d[2 * j], d[2 * j + 1]));
            }
            const unsigned wb = __reduce_max_sync(0xffffffffu, __float_as_uint(mm));
            unsigned cl = 0;
#pragma unroll
            for (int t = 0; t < 16; t++)
                if (__float_as_uint(d[t]) == wb) cl = max(cl, ~(unsigned)io[t]);
            const unsigned wl = __reduce_max_sync(0xffffffffu, cl);
            mykey = ((ull)wb << 32) | wl;
            wmaxf = __uint_as_float(wb);
        }
        if (lane == 0) s_key[i & 1][wid] = mykey;
    }
}

// ============================================================================
// Kernel 2: ball query + top-K (unchanged)
// ============================================================================
__global__ __launch_bounds__(256) void bq_kernel(const float* __restrict__ pos) {
    __shared__ float s_d2[8][CAP];
    __shared__ int   s_idx[8][CAP];

    const int w = threadIdx.x >> 5;
    const int lane = threadIdx.x & 31;
    const int c = blockIdx.x * 8 + w;
    const int e = c >> 11;
    const float* pe = pos + (size_t)e * NP * 3;

    const float cx = g_centers[c * 3 + 0];
    const float cy = g_centers[c * 3 + 1];
    const float cz = g_centers[c * 3 + 2];

    int cnt = 0;
    const unsigned lmask = (1u << lane) - 1u;
    for (int j = lane; j < NP; j += 32) {
        const float d2v = dist2(pe[3 * j] - cx, pe[3 * j + 1] - cy, pe[3 * j + 2] - cz);
        const bool inr = (d2v <= R2F);
        const unsigned mball = __ballot_sync(0xffffffffu, inr);
        if (inr) {
            const int slot = cnt + __popc(mball & lmask);
            if (slot < CAP) { s_d2[w][slot] = d2v; s_idx[w][slot] = j; }
        }
        cnt += __popc(mball);
    }
    const int C = (cnt < CAP) ? cnt : CAP;

    if (C <= KNN) {
        for (int k = lane; k < KNN; k += 32)
            g_nbr[c * KNN + k] = (k < C) ? s_idx[w][k] : 0;
        if (lane == 0) g_cnt[c] = C;
    } else {
        for (int s = 0; s < KNN; s++) {
            ull best = ~0ull;
            for (int t = lane; t < C; t += 32) {
                const ull key = ((ull)__float_as_uint(s_d2[w][t]) << 32) | (unsigned)t;
                best = (key < best) ? key : best;
            }
#pragma unroll
            for (int o = 16; o > 0; o >>= 1) {
                const ull other = __shfl_down_sync(0xffffffffu, best, o);
                best = (other < best) ? other : best;
            }
            best = __shfl_sync(0xffffffffu, best, 0);
            const int slot = (int)(unsigned)best;
            if (lane == 0) {
                g_nbr[c * KNN + s] = s_idx[w][slot];
                s_d2[w][slot] = BIGF;
            }
            __syncwarp();
        }
        if (lane == 0) g_cnt[c] = KNN;
    }
}

// ============================================================================
// Kernel 0b: U = b1 + x @ W1[0:32]  (unchanged)
// ============================================================================
__global__ __launch_bounds__(256) void upre_kernel(
    const float* __restrict__ x, const float* __restrict__ W1,
    const float* __restrict__ b1)
{
    __shared__ float sW[32 * 64];
    __shared__ float sb[64];
    const int tid = threadIdx.x;
    for (int i = tid; i < 2048; i += 256) sW[i] = W1[i];
    if (tid < 64) sb[tid] = b1[tid];
    __syncthreads();

    const int row = blockIdx.x * 256 + tid;
    float inv[32];
    const float4* xr = (const float4*)(x + (size_t)row * 32);
#pragma unroll
    for (int q = 0; q < 8; q++) {
        const float4 v = xr[q];
        inv[4 * q] = v.x; inv[4 * q + 1] = v.y; inv[4 * q + 2] = v.z; inv[4 * q + 3] = v.w;
    }
    float4* ur = (float4*)(g_U + (size_t)row * 64);
#pragma unroll
    for (int h = 0; h < 2; h++) {
        ull acc[16];
#pragma unroll
        for (int k = 0; k < 8; k++) {
            const ulonglong2 bb = *(const ulonglong2*)(sb + h * 32 + 4 * k);
            acc[2 * k] = bb.x; acc[2 * k + 1] = bb.y;
        }
#pragma unroll
        for (int i = 0; i < 32; i++) {
            const ull a = pack2(inv[i]);
#pragma unroll
            for (int k = 0; k < 8; k++) {
                const ulonglong2 wv = *(const ulonglong2*)(sW + i * 64 + h * 32 + 4 * k);
                FMA2(acc[2 * k], a, wv.x);
                FMA2(acc[2 * k + 1], a, wv.y);
            }
        }
#pragma unroll
        for (int k = 0; k < 8; k++) {
            const float2 v0 = unpack2(acc[2 * k]);
            const float2 v1 = unpack2(acc[2 * k + 1]);
            ur[h * 8 + k] = make_float4(v0.x, v0.y, v1.x, v1.y);
        }
    }
}

// ============================================================================
// Kernel 3: gather + MLP + max-pool (unchanged from R3)
// ============================================================================
__global__ __launch_bounds__(128, 3) void mlp_kernel(
    const float* __restrict__ pos,
    const float* __restrict__ W1,
    const float* __restrict__ W2, const float* __restrict__ b2,
    const float* __restrict__ W3, const float* __restrict__ b3,
    float* __restrict__ out)
{
    extern __shared__ float smem[];
    float* sW1p = smem;            // 192
    float* sW2 = sW1p + 192;       // 4096
    float* sW3 = sW2 + 4096;       // 8192
    float* sb2 = sW3 + 8192;       // 64
    float* sb3 = sb2 + 64;         // 128
    int*   sOut = (int*)(sb3 + 128);

    const int tid = threadIdx.x;
    for (int i = tid; i < 192; i += 128) sW1p[i] = W1[2048 + i];
    for (int i = tid; i < 4096; i += 128) sW2[i] = W2[i];
    for (int i = tid; i < 8192; i += 128) sW3[i] = W3[i];
    if (tid < 64) sb2[tid] = b2[tid];
    sb3[tid] = b3[tid];
    sOut[tid] = 0;
    sOut[tid + 128] = 0;
    __syncthreads();

    const int cl = tid >> 6;
    const int n  = tid & 63;
    const int lane = tid & 31;
    const int c  = blockIdx.x * 2 + cl;
    const int e  = c >> 11;
    const bool active = (n < g_cnt[c]);
    int* sOutC = sOut + cl * 128;

    const int idx = g_nbr[c * KNN + n];
    const int row = e * NP + idx;

    float rel[3];
    rel[0] = pos[row * 3 + 0] - g_centers[c * 3 + 0];
    rel[1] = pos[row * 3 + 1] - g_centers[c * 3 + 1];
    rel[2] = pos[row * 3 + 2] - g_centers[c * 3 + 2];

    float h1[64];
    const float4* ur = (const float4*)(g_U + (size_t)row * 64);
#pragma unroll
    for (int h = 0; h < 2; h++) {
        ull acc[16];
#pragma unroll
        for (int q = 0; q < 8; q++) {
            const float4 u = ur[h * 8 + q];
            acc[2 * q]     = packf2(u.x, u.y);
            acc[2 * q + 1] = packf2(u.z, u.w);
        }
#pragma unroll
        for (int i = 0; i < 3; i++) {
            const ull a = pack2(rel[i]);
#pragma unroll
            for (int k = 0; k < 8; k++) {
                const ulonglong2 wv = *(const ulonglong2*)(sW1p + i * 64 + h * 32 + 4 * k);
                FMA2(acc[2 * k], a, wv.x);
                FMA2(acc[2 * k + 1], a, wv.y);
            }
        }
#pragma unroll
        for (int k = 0; k < 16; k++) {
            const float2 v = unpack2(acc[k]);
            h1[h * 32 + 2 * k]     = fmaxf(v.x, 0.f);
            h1[h * 32 + 2 * k + 1] = fmaxf(v.y, 0.f);
        }
    }

    float h2[64];
#pragma unroll
    for (int q = 0; q < 4; q++) {
        ull acc[8];
#pragma unroll
        for (int k = 0; k < 4; k++) {
            const ulonglong2 bb = *(const ulonglong2*)(sb2 + q * 16 + 4 * k);
            acc[2 * k] = bb.x; acc[2 * k + 1] = bb.y;
        }
#pragma unroll
        for (int i = 0; i < 64; i++) {
            const ull a = pack2(h1[i]);
#pragma unroll
            for (int k = 0; k < 4; k++) {
                const ulonglong2 wv = *(const ulonglong2*)(sW2 + i * 64 + q * 16 + 4 * k);
                FMA2(acc[2 * k], a, wv.x);
                FMA2(acc[2 * k + 1], a, wv.y);
            }
        }
#pragma unroll
        for (int k = 0; k < 8; k++) {
            const float2 v = unpack2(acc[k]);
            h2[q * 16 + 2 * k]     = fmaxf(v.x, 0.f);
            h2[q * 16 + 2 * k + 1] = fmaxf(v.y, 0.f);
        }
    }

#pragma unroll
    for (int qd = 0; qd < 4; qd++) {
        ull acc[16];
#pragma unroll
        for (int k = 0; k < 8; k++) {
            const ulonglong2 bb = *(const ulonglong2*)(sb3 + qd * 32 + 4 * k);
            acc[2 * k] = bb.x; acc[2 * k + 1] = bb.y;
        }
#pragma unroll
        for (int i = 0; i < 64; i++) {
            const ull a = pack2(h2[i]);
#pragma unroll
            for (int k = 0; k < 8; k++) {
                const ulonglong2 wv = *(const ulonglong2*)(sW3 + i * 128 + qd * 32 + 4 * k);
                FMA2(acc[2 * k], a, wv.x);
                FMA2(acc[2 * k + 1], a, wv.y);
            }
        }
#pragma unroll
        for (int k = 0; k < 16; k++) {
            const float2 v = unpack2(acc[k]);
            float v0 = active ? fmaxf(v.x, 0.f) : 0.f;
            float v1 = active ? fmaxf(v.y, 0.f) : 0.f;
#pragma unroll
            for (int o = 16; o >= 4; o >>= 1) {
                v0 = fmaxf(v0, __shfl_xor_sync(0xffffffffu, v0, o));
                v1 = fmaxf(v1, __shfl_xor_sync(0xffffffffu, v1, o));
            }
            if (lane < 4) {
                atomicMax(sOutC + qd * 32 + 2 * k,     __float_as_int(v0));
                atomicMax(sOutC + qd * 32 + 2 * k + 1, __float_as_int(v1));
            }
        }
    }
    __syncthreads();

    {
        int i = tid;
        int cc = blockIdx.x * 2 + (i >> 7);
        out[(size_t)cc * 128 + (i & 127)] = __int_as_float(sOut[i]);
        i = tid + 128;
        cc = blockIdx.x * 2 + (i >> 7);
        out[(size_t)cc * 128 + (i & 127)] = __int_as_float(sOut[i]);
    }
    if (tid < 6) {
        const int cc = blockIdx.x * 2 + (tid / 3);
        out[POS_OFF + (size_t)cc * 3 + (tid % 3)] = g_centers[cc * 3 + (tid % 3)];
    }
    if (tid < 2) {
        const int cc = blockIdx.x * 2 + tid;
        out[BATCH_OFF + cc] = (float)(cc >> 11);
    }
}

// ============================================================================
extern "C" void kernel_launch(void* const* d_in, const int* in_sizes, int n_in,
                              void* d_out, int out_size) {
    const float* x   = (const float*)d_in[0];
    const float* pos = (const float*)d_in[1];
    const float* W1 = (const float*)d_in[3];
    const float* b1 = (const float*)d_in[4];
    const float* W2 = (const float*)d_in[5];
    const float* b2 = (const float*)d_in[6];
    const float* W3 = (const float*)d_in[7];
    const float* b3 = (const float*)d_in[8];
    float* out = (float*)d_out;

    const int fps_smem = 4 * NP * 4;   // 131072 B
    cudaFuncSetAttribute(fps_kernel, cudaFuncAttributeMaxDynamicSharedMemorySize,
                         fps_smem);
    fps_kernel<<<B_EV, FT, fps_smem>>>(pos);

    upre_kernel<<<(B_EV * NP) / 256, 256>>>(x, W1, b1);
    bq_kernel<<<NC / 8, 256>>>(pos);

    const int mlp_smem = (192 + 4096 + 8192 + 64 + 128 + 256) * 4;
    cudaFuncSetAttribute(mlp_kernel, cudaFuncAttributeMaxDynamicSharedMemorySize,
                         mlp_smem);
    mlp_kernel<<<NC / 2, 128, mlp_smem>>>(pos, W1, W2, b2, W3, b3, out);
}

// round 7
// speedup vs baseline: 2.1154x; 1.0250x over previous
#include <cuda_runtime.h>
#include <cstdint>

#define B_EV 4
#define NP 8192
#define MP 2048
#define KNN 64
#define NC (B_EV * MP)
#define R2F 0.04f
#define BIGF 1e10f
#define CAP 512

#define XLEN (NC * 128)
#define POS_OFF XLEN
#define BATCH_OFF (XLEN + NC * 3)

typedef unsigned long long ull;

__device__ float g_centers[NC * 3];
__device__ int   g_nbr[NC * KNN];
__device__ int   g_cnt[NC];
__device__ float g_U[B_EV * NP * 64];

__device__ __forceinline__ float dist2(float dx, float dy, float dz) {
    return __fadd_rn(__fadd_rn(__fmul_rn(dx, dx), __fmul_rn(dy, dy)),
                     __fmul_rn(dz, dz));
}

#define FMA2(acc, a, b) \
    asm("fma.rn.f32x2 %0, %1, %2, %0;" : "+l"(acc) : "l"(a), "l"(b))
#define ADD2(dst, a, b) \
    asm("add.rn.f32x2 %0, %1, %2;" : "=l"(dst) : "l"(a), "l"(b))
#define MUL2(dst, a, b) \
    asm("mul.rn.f32x2 %0, %1, %2;" : "=l"(dst) : "l"(a), "l"(b))

__device__ __forceinline__ ull pack2(float v) {
    ull r; asm("mov.b64 %0, {%1, %1};" : "=l"(r) : "r"(__float_as_uint(v)));
    return r;
}
__device__ __forceinline__ ull packf2(float lo, float hi) {
    ull r; asm("mov.b64 %0, {%1, %2};" : "=l"(r)
        : "r"(__float_as_uint(lo)), "r"(__float_as_uint(hi)));
    return r;
}
__device__ __forceinline__ float2 unpack2(ull p) {
    unsigned lo, hi; asm("mov.b64 {%0, %1}, %2;" : "=r"(lo), "=r"(hi) : "l"(p));
    return make_float2(__uint_as_float(lo), __uint_as_float(hi));
}

// ============================================================================
// Kernel 1: FPS. 512 threads x 16 pts, Morton counting-sort.
// Per-THREAD bbox pruning: thread's whole update is provably a no-op iff
// lb2(thread bbox, c) >= thread dmax (1e-6-deflated sound bound); the warp
// issues the update only if any lane is active. One barrier/iter; selection
// via double-buffered per-warp keys (d_bits<<32 | ~orig_idx) + two redux.max
// -> max d, ties to lowest original index (== jnp.argmax). All d-values
// follow the exact reference rounding chain.
// ============================================================================
#define FT 512

__global__ __launch_bounds__(FT) void fps_kernel(const float* __restrict__ pos) {
    const int e = blockIdx.x;
    const float* pe = pos + (size_t)e * NP * 3;
    const int tid = threadIdx.x;
    const int lane = tid & 31;
    const int wid = tid >> 5;

    extern __shared__ float sm[];
    float* sx = sm;
    float* sy = sx + NP;
    float* sz = sy + NP;
    int*   sidx = (int*)(sz + NP);
    __shared__ int s_cnt[64];
    __shared__ ull s_key[2][16];

    if (tid < 64) s_cnt[tid] = 0;
    __syncthreads();

    float ox[16], oy[16], oz[16];
    int cel[16];
#pragma unroll
    for (int t = 0; t < 16; t++) {
        const int j = tid + t * FT;
        ox[t] = pe[3 * j]; oy[t] = pe[3 * j + 1]; oz[t] = pe[3 * j + 2];
        int ix = (int)(ox[t] * 4.f); ix = ix < 3 ? ix : 3;
        int iy = (int)(oy[t] * 4.f); iy = iy < 3 ? iy : 3;
        int iz = (int)(oz[t] * 4.f); iz = iz < 3 ? iz : 3;
        cel[t] = ((ix >> 1) << 5) | ((iy >> 1) << 4) | ((iz >> 1) << 3) |
                 ((ix & 1) << 2) | ((iy & 1) << 1) | (iz & 1);
        atomicAdd(&s_cnt[cel[t]], 1);
    }
    __syncthreads();
    if (tid == 0) {
        int run = 0;
        for (int c2 = 0; c2 < 64; c2++) { const int v = s_cnt[c2]; s_cnt[c2] = run; run += v; }
    }
    __syncthreads();
#pragma unroll
    for (int t = 0; t < 16; t++) {
        const int p = atomicAdd(&s_cnt[cel[t]], 1);
        sx[p] = ox[t]; sy[p] = oy[t]; sz[p] = oz[t]; sidx[p] = tid + t * FT;
    }
    __syncthreads();

    ull pxp[8], pyp[8], pzp[8];
    int io[16];
    float d[16];
    float tbnx = 2.f, tbny = 2.f, tbnz = 2.f, tbxx = -1.f, tbxy = -1.f, tbxz = -1.f;
    const int base = tid * 16;
#pragma unroll
    for (int j = 0; j < 8; j++) {
        const float ax = sx[base + 2 * j], bx = sx[base + 2 * j + 1];
        const float ay = sy[base + 2 * j], by = sy[base + 2 * j + 1];
        const float az = sz[base + 2 * j], bz = sz[base + 2 * j + 1];
        pxp[j] = packf2(ax, bx); pyp[j] = packf2(ay, by); pzp[j] = packf2(az, bz);
        io[2 * j] = sidx[base + 2 * j]; io[2 * j + 1] = sidx[base + 2 * j + 1];
        tbnx = fminf(tbnx, fminf(ax, bx)); tbxx = fmaxf(tbxx, fmaxf(ax, bx));
        tbny = fminf(tbny, fminf(ay, by)); tbxy = fmaxf(tbxy, fmaxf(ay, by));
        tbnz = fminf(tbnz, fminf(az, bz)); tbxz = fmaxf(tbxz, fmaxf(az, bz));
    }
    __syncthreads();   // sorted reads done -> repurpose buffers

    // orig-indexed position copy for O(LDS) next-center lookup
#pragma unroll
    for (int t = 0; t < 16; t++) {
        const int j = tid + t * FT;
        sx[j] = ox[t]; sy[j] = oy[t]; sz[j] = oz[t];
    }

    const float c0x = pe[0], c0y = pe[1], c0z = pe[2];
    {
        const ull ncx = pack2(-c0x), ncy = pack2(-c0y), ncz = pack2(-c0z);
#pragma unroll
        for (int j = 0; j < 8; j++) {
            ull dx, dy, dz, qx, qy, qz, s1, s2;
            ADD2(dx, pxp[j], ncx); ADD2(dy, pyp[j], ncy); ADD2(dz, pzp[j], ncz);
            MUL2(qx, dx, dx); MUL2(qy, dy, dy); MUL2(qz, dz, dz);
            ADD2(s1, qx, qy); ADD2(s2, s1, qz);
            const float2 f = unpack2(s2);
            d[2 * j] = f.x; d[2 * j + 1] = f.y;
        }
    }
    ull mykey;
    float tdmax;
    {
        float mm = d[0];
#pragma unroll
        for (int t = 1; t < 16; t++) mm = fmaxf(mm, d[t]);
        tdmax = mm;
        const unsigned wb = __reduce_max_sync(0xffffffffu, __float_as_uint(mm));
        unsigned cl = 0;
#pragma unroll
        for (int t = 0; t < 16; t++)
            if (__float_as_uint(d[t]) == wb) cl = max(cl, ~(unsigned)io[t]);
        const unsigned wl = __reduce_max_sync(0xffffffffu, cl);
        mykey = ((ull)wb << 32) | wl;
    }
    if (lane == 0) s_key[0][wid] = mykey;
    if (tid == 0) {
        g_centers[(e * MP) * 3 + 0] = c0x;
        g_centers[(e * MP) * 3 + 1] = c0y;
        g_centers[(e * MP) * 3 + 2] = c0z;
    }

    for (int i = 1; i < MP; i++) {
        __syncthreads();
        const ull kk = s_key[(i - 1) & 1][lane & 15];
        const unsigned hi = (unsigned)(kk >> 32);
        const unsigned lo = (unsigned)kk;
        const unsigned mhi = __reduce_max_sync(0xffffffffu, hi);
        const unsigned mlo = __reduce_max_sync(0xffffffffu, (hi == mhi) ? lo : 0u);
        const int nxt = (int)(~mlo);

        const float nx = sx[nxt], ny = sy[nxt], nz = sz[nxt];
        if (tid == 0) {
            g_centers[(e * MP + i) * 3 + 0] = nx;
            g_centers[(e * MP + i) * 3 + 1] = ny;
            g_centers[(e * MP + i) * 3 + 2] = nz;
        }

        const float lbx = fmaxf(fmaxf(tbnx - nx, nx - tbxx), 0.f);
        const float lby = fmaxf(fmaxf(tbny - ny, ny - tbxy), 0.f);
        const float lbz = fmaxf(fmaxf(tbnz - nz, nz - tbxz), 0.f);
        const float lb2 = ((lbx * lbx + lby * lby) + lbz * lbz) * 0.999999f;
        const bool needs = (lb2 < tdmax);

        if (__any_sync(0xffffffffu, needs)) {
            const ull ncx = pack2(-nx), ncy = pack2(-ny), ncz = pack2(-nz);
            float mm = 0.f;
#pragma unroll
            for (int j = 0; j < 8; j++) {
                ull dx, dy, dz, qx, qy, qz, s1, s2;
                ADD2(dx, pxp[j], ncx); ADD2(dy, pyp[j], ncy); ADD2(dz, pzp[j], ncz);
                MUL2(qx, dx, dx); MUL2(qy, dy, dy); MUL2(qz, dz, dz);
                ADD2(s1, qx, qy); ADD2(s2, s1, qz);
                const float2 f = unpack2(s2);
                d[2 * j]     = fminf(d[2 * j], f.x);
                d[2 * j + 1] = fminf(d[2 * j + 1], f.y);
                mm = fmaxf(mm, fmaxf(d[2 * j], d[2 * j + 1]));
            }
            tdmax = mm;
            const unsigned wb = __reduce_max_sync(0xffffffffu, __float_as_uint(mm));
            unsigned cl = 0;
#pragma unroll
            for (int t = 0; t < 16; t++)
                if (__float_as_uint(d[t]) == wb) cl = max(cl, ~(unsigned)io[t]);
            const unsigned wl = __reduce_max_sync(0xffffffffu, cl);
            mykey = ((ull)wb << 32) | wl;
        }
        if (lane == 0) s_key[i & 1][wid] = mykey;
    }
}

// ============================================================================
// Kernel 2: ball query + top-K (unchanged)
// ============================================================================
__global__ __launch_bounds__(256) void bq_kernel(const float* __restrict__ pos) {
    __shared__ float s_d2[8][CAP];
    __shared__ int   s_idx[8][CAP];

    const int w = threadIdx.x >> 5;
    const int lane = threadIdx.x & 31;
    const int c = blockIdx.x * 8 + w;
    const int e = c >> 11;
    const float* pe = pos + (size_t)e * NP * 3;

    const float cx = g_centers[c * 3 + 0];
    const float cy = g_centers[c * 3 + 1];
    const float cz = g_centers[c * 3 + 2];

    int cnt = 0;
    const unsigned lmask = (1u << lane) - 1u;
    for (int j = lane; j < NP; j += 32) {
        const float d2v = dist2(pe[3 * j] - cx, pe[3 * j + 1] - cy, pe[3 * j + 2] - cz);
        const bool inr = (d2v <= R2F);
        const unsigned mball = __ballot_sync(0xffffffffu, inr);
        if (inr) {
            const int slot = cnt + __popc(mball & lmask);
            if (slot < CAP) { s_d2[w][slot] = d2v; s_idx[w][slot] = j; }
        }
        cnt += __popc(mball);
    }
    const int C = (cnt < CAP) ? cnt : CAP;

    if (C <= KNN) {
        for (int k = lane; k < KNN; k += 32)
            g_nbr[c * KNN + k] = (k < C) ? s_idx[w][k] : 0;
        if (lane == 0) g_cnt[c] = C;
    } else {
        for (int s = 0; s < KNN; s++) {
            ull best = ~0ull;
            for (int t = lane; t < C; t += 32) {
                const ull key = ((ull)__float_as_uint(s_d2[w][t]) << 32) | (unsigned)t;
                best = (key < best) ? key : best;
            }
#pragma unroll
            for (int o = 16; o > 0; o >>= 1) {
                const ull other = __shfl_down_sync(0xffffffffu, best, o);
                best = (other < best) ? other : best;
            }
            best = __shfl_sync(0xffffffffu, best, 0);
            const int slot = (int)(unsigned)best;
            if (lane == 0) {
                g_nbr[c * KNN + s] = s_idx[w][slot];
                s_d2[w][slot] = BIGF;
            }
            __syncwarp();
        }
        if (lane == 0) g_cnt[c] = KNN;
    }
}

// ============================================================================
// Kernel 0b: U = b1 + x @ W1[0:32]  (unchanged)
// ============================================================================
__global__ __launch_bounds__(256) void upre_kernel(
    const float* __restrict__ x, const float* __restrict__ W1,
    const float* __restrict__ b1)
{
    __shared__ float sW[32 * 64];
    __shared__ float sb[64];
    const int tid = threadIdx.x;
    for (int i = tid; i < 2048; i += 256) sW[i] = W1[i];
    if (tid < 64) sb[tid] = b1[tid];
    __syncthreads();

    const int row = blockIdx.x * 256 + tid;
    float inv[32];
    const float4* xr = (const float4*)(x + (size_t)row * 32);
#pragma unroll
    for (int q = 0; q < 8; q++) {
        const float4 v = xr[q];
        inv[4 * q] = v.x; inv[4 * q + 1] = v.y; inv[4 * q + 2] = v.z; inv[4 * q + 3] = v.w;
    }
    float4* ur = (float4*)(g_U + (size_t)row * 64);
#pragma unroll
    for (int h = 0; h < 2; h++) {
        ull acc[16];
#pragma unroll
        for (int k = 0; k < 8; k++) {
            const ulonglong2 bb = *(const ulonglong2*)(sb + h * 32 + 4 * k);
            acc[2 * k] = bb.x; acc[2 * k + 1] = bb.y;
        }
#pragma unroll
        for (int i = 0; i < 32; i++) {
            const ull a = pack2(inv[i]);
#pragma unroll
            for (int k = 0; k < 8; k++) {
                const ulonglong2 wv = *(const ulonglong2*)(sW + i * 64 + h * 32 + 4 * k);
                FMA2(acc[2 * k], a, wv.x);
                FMA2(acc[2 * k + 1], a, wv.y);
            }
        }
#pragma unroll
        for (int k = 0; k < 8; k++) {
            const float2 v0 = unpack2(acc[2 * k]);
            const float2 v1 = unpack2(acc[2 * k + 1]);
            ur[h * 8 + k] = make_float4(v0.x, v0.y, v1.x, v1.y);
        }
    }
}

// ============================================================================
// Kernel 3: gather + MLP + max-pool (reverted to R5 known-good: regs=168,
// zero spill, 497us)
// ============================================================================
__global__ __launch_bounds__(128, 3) void mlp_kernel(
    const float* __restrict__ pos,
    const float* __restrict__ W1,
    const float* __restrict__ W2, const float* __restrict__ b2,
    const float* __restrict__ W3, const float* __restrict__ b3,
    float* __restrict__ out)
{
    extern __shared__ float smem[];
    float* sW1p = smem;            // 192
    float* sW2 = sW1p + 192;       // 4096
    float* sW3 = sW2 + 4096;       // 8192
    float* sb2 = sW3 + 8192;       // 64
    float* sb3 = sb2 + 64;         // 128
    int*   sOut = (int*)(sb3 + 128);

    const int tid = threadIdx.x;
    for (int i = tid; i < 192; i += 128) sW1p[i] = W1[2048 + i];
    for (int i = tid; i < 4096; i += 128) sW2[i] = W2[i];
    for (int i = tid; i < 8192; i += 128) sW3[i] = W3[i];
    if (tid < 64) sb2[tid] = b2[tid];
    sb3[tid] = b3[tid];
    sOut[tid] = 0;
    sOut[tid + 128] = 0;
    __syncthreads();

    const int cl = tid >> 6;
    const int n  = tid & 63;
    const int lane = tid & 31;
    const int c  = blockIdx.x * 2 + cl;
    const int e  = c >> 11;
    const bool active = (n < g_cnt[c]);
    int* sOutC = sOut + cl * 128;

    const int idx = g_nbr[c * KNN + n];
    const int row = e * NP + idx;

    float rel[3];
    rel[0] = pos[row * 3 + 0] - g_centers[c * 3 + 0];
    rel[1] = pos[row * 3 + 1] - g_centers[c * 3 + 1];
    rel[2] = pos[row * 3 + 2] - g_centers[c * 3 + 2];

    float h1[64];
    const float4* ur = (const float4*)(g_U + (size_t)row * 64);
#pragma unroll
    for (int h = 0; h < 2; h++) {
        ull acc[16];
#pragma unroll
        for (int q = 0; q < 8; q++) {
            const float4 u = ur[h * 8 + q];
            acc[2 * q]     = packf2(u.x, u.y);
            acc[2 * q + 1] = packf2(u.z, u.w);
        }
#pragma unroll
        for (int i = 0; i < 3; i++) {
            const ull a = pack2(rel[i]);
#pragma unroll
            for (int k = 0; k < 8; k++) {
                const ulonglong2 wv = *(const ulonglong2*)(sW1p + i * 64 + h * 32 + 4 * k);
                FMA2(acc[2 * k], a, wv.x);
                FMA2(acc[2 * k + 1], a, wv.y);
            }
        }
#pragma unroll
        for (int k = 0; k < 16; k++) {
            const float2 v = unpack2(acc[k]);
            h1[h * 32 + 2 * k]     = fmaxf(v.x, 0.f);
            h1[h * 32 + 2 * k + 1] = fmaxf(v.y, 0.f);
        }
    }

    float h2[64];
#pragma unroll
    for (int q = 0; q < 4; q++) {
        ull acc[8];
#pragma unroll
        for (int k = 0; k < 4; k++) {
            const ulonglong2 bb = *(const ulonglong2*)(sb2 + q * 16 + 4 * k);
            acc[2 * k] = bb.x; acc[2 * k + 1] = bb.y;
        }
#pragma unroll
        for (int i = 0; i < 64; i++) {
            const ull a = pack2(h1[i]);
#pragma unroll
            for (int k = 0; k < 4; k++) {
                const ulonglong2 wv = *(const ulonglong2*)(sW2 + i * 64 + q * 16 + 4 * k);
                FMA2(acc[2 * k], a, wv.x);
                FMA2(acc[2 * k + 1], a, wv.y);
            }
        }
#pragma unroll
        for (int k = 0; k < 8; k++) {
            const float2 v = unpack2(acc[k]);
            h2[q * 16 + 2 * k]     = fmaxf(v.x, 0.f);
            h2[q * 16 + 2 * k + 1] = fmaxf(v.y, 0.f);
        }
    }

#pragma unroll
    for (int qd = 0; qd < 4; qd++) {
        ull acc[16];
#pragma unroll
        for (int k = 0; k < 8; k++) {
            const ulonglong2 bb = *(const ulonglong2*)(sb3 + qd * 32 + 4 * k);
            acc[2 * k] = bb.x; acc[2 * k + 1] = bb.y;
        }
#pragma unroll
        for (int i = 0; i < 64; i++) {
            const ull a = pack2(h2[i]);
#pragma unroll
            for (int k = 0; k < 8; k++) {
                const ulonglong2 wv = *(const ulonglong2*)(sW3 + i * 128 + qd * 32 + 4 * k);
                FMA2(acc[2 * k], a, wv.x);
                FMA2(acc[2 * k + 1], a, wv.y);
            }
        }
#pragma unroll
        for (int k = 0; k < 16; k++) {
            const float2 v = unpack2(acc[k]);
            float v0 = active ? fmaxf(v.x, 0.f) : 0.f;
            float v1 = active ? fmaxf(v.y, 0.f) : 0.f;
#pragma unroll
            for (int o = 16; o >= 4; o >>= 1) {
                v0 = fmaxf(v0, __shfl_xor_sync(0xffffffffu, v0, o));
                v1 = fmaxf(v1, __shfl_xor_sync(0xffffffffu, v1, o));
            }
            if (lane < 4) {
                atomicMax(sOutC + qd * 32 + 2 * k,     __float_as_int(v0));
                atomicMax(sOutC + qd * 32 + 2 * k + 1, __float_as_int(v1));
            }
        }
    }
    __syncthreads();

    {
        int i = tid;
        int cc = blockIdx.x * 2 + (i >> 7);
        out[(size_t)cc * 128 + (i & 127)] = __int_as_float(sOut[i]);
        i = tid + 128;
        cc = blockIdx.x * 2 + (i >> 7);
        out[(size_t)cc * 128 + (i & 127)] = __int_as_float(sOut[i]);
    }
    if (tid < 6) {
        const int cc = blockIdx.x * 2 + (tid / 3);
        out[POS_OFF + (size_t)cc * 3 + (tid % 3)] = g_centers[cc * 3 + (tid % 3)];
    }
    if (tid < 2) {
        const int cc = blockIdx.x * 2 + tid;
        out[BATCH_OFF + cc] = (float)(cc >> 11);
    }
}

// ============================================================================
extern "C" void kernel_launch(void* const* d_in, const int* in_sizes, int n_in,
                              void* d_out, int out_size) {
    const float* x   = (const float*)d_in[0];
    const float* pos = (const float*)d_in[1];
    const float* W1 = (const float*)d_in[3];
    const float* b1 = (const float*)d_in[4];
    const float* W2 = (const float*)d_in[5];
    const float* b2 = (const float*)d_in[6];
    const float* W3 = (const float*)d_in[7];
    const float* b3 = (const float*)d_in[8];
    float* out = (float*)d_out;

    const int fps_smem = 4 * NP * 4;
    cudaFuncSetAttribute(fps_kernel, cudaFuncAttributeMaxDynamicSharedMemorySize,
                         fps_smem);
    fps_kernel<<<B_EV, FT, fps_smem>>>(pos);

    upre_kernel<<<(B_EV * NP) / 256, 256>>>(x, W1, b1);
    bq_kernel<<<NC / 8, 256>>>(pos);

    const int mlp_smem = (192 + 4096 + 8192 + 64 + 128 + 256) * 4;
    cudaFuncSetAttribute(mlp_kernel, cudaFuncAttributeMaxDynamicSharedMemorySize,
                         mlp_smem);
    mlp_kernel<<<NC / 2, 128, mlp_smem>>>(pos, W1, W2, b2, W3, b3, out);
}